// round 6
// baseline (speedup 1.0000x reference)
#include <cuda_runtime.h>
#include <math.h>
#include <stdint.h>

#define TB 1024
#define HD 1024
#define NHQ 16
#define NHKV 4
#define DH 64
#define SEQ 512
#define NB 2
#define NE 8
#define ID 4096
#define KT 16
#define STAGES 4

// ---- scratch (padded +16 floats where used as GEMM A/BT source) ----
__device__ float g_h [TB*HD + 16];
__device__ float g_q [TB*NHQ*DH + 16];
__device__ float g_k [TB*NHKV*DH + 16];
__device__ float g_v [TB*NHKV*DH + 16];
__device__ float g_sc[(size_t)NB*NHQ*SEQ*SEQ + 16];
__device__ float g_ao[TB*NHQ*DH + 16];
__device__ float g_x2[TB*HD + 16];
__device__ float g_t [TB*HD + 16];
__device__ int   g_cnt[NE];
__device__ int   g_rows[NE*TB];
__device__ int   g_se[TB*2];
__device__ int   g_sr[TB*2];
__device__ float g_sp[TB*2];
__device__ float g_gt [(size_t)NE*TB*ID + 16];
__device__ float g_act[(size_t)NE*TB*ID + 16];
__device__ float g_dn [(size_t)NE*TB*HD + 16];

// ---- primitives ----
__device__ __forceinline__ uint32_t tf32cvt(float x){
    uint32_t u; asm("cvt.rna.tf32.f32 %0, %1;" : "=r"(u) : "f"(x)); return u;
}
__device__ __forceinline__ void mma8(float* d, const uint32_t* a, uint32_t b0, uint32_t b1){
    asm volatile("mma.sync.aligned.m16n8k8.row.col.f32.tf32.tf32.f32 "
        "{%0,%1,%2,%3},{%4,%5,%6,%7},{%8,%9},{%0,%1,%2,%3};"
        : "+f"(d[0]),"+f"(d[1]),"+f"(d[2]),"+f"(d[3])
        : "r"(a[0]),"r"(a[1]),"r"(a[2]),"r"(a[3]),"r"(b0),"r"(b1));
}
__device__ __forceinline__ uint32_t smem_u32(const void* p){
    uint32_t a; asm("{ .reg .u64 t; cvta.to.shared.u64 t, %1; cvt.u32.u64 %0, t; }" : "=r"(a) : "l"(p)); return a;
}
#define CP16(d,s) asm volatile("cp.async.cg.shared.global [%0],[%1],16;"::"r"(d),"l"(s))
#define CP8(d,s)  asm volatile("cp.async.ca.shared.global [%0],[%1],8;"::"r"(d),"l"(s))
#define CPCOMMIT() asm volatile("cp.async.commit_group;":::"memory")
#define CPWAIT(n)  asm volatile("cp.async.wait_group %0;"::"n"(n):"memory")

// ================== pipelined tf32 MMA mainloop ==================
// BM=128, BN=NI*32, KT=16, 4-stage cp.async. 8 warps (2m x 4n), warp tile 64 x NI*8.
// A smem: [128 rows][pitch 20 floats] (banks 20q+c distinct).
// B smem NN: [16 k][pitch NI*32+8 floats] (row stride ≡ 8 mod 32 banks -> conflict-free).
// B smem NT: rows like A (pitch 20).
template<int NI, bool BTRANS, bool GATHER>
__device__ __forceinline__ void tc_loop(float (&acc)[4][NI][4],
    const float* __restrict__ A, int lda, const int* srow, int rm,
    const float* __restrict__ B, int ldb, int bn, int K, char* sm)
{
    const int BPITCH = NI*32 + 8;                    // floats (NN)
    const int BSTG = BTRANS ? 10240 : KT*BPITCH*4;   // bytes
    const int STG  = 10240 + BSTG;
    const int tid = threadIdx.x, lane = tid & 31;
    const int wm = (tid>>5)>>2, wn = (tid>>5)&3, q = lane>>2, s = lane&3;
#pragma unroll
    for (int i=0;i<4;i++)
#pragma unroll
        for (int j=0;j<NI;j++)
#pragma unroll
            for (int r=0;r<4;r++) acc[i][j][r]=0.f;

    const uint32_t smb = smem_u32(sm);
    const int arow = tid>>1, ah = tid&1;
    int agr = GATHER ? srow[arow] : rm + arow;
    const float* asrc = A + (size_t)agr*lda + ah*10;
    const uint32_t adst = smb + arow*80 + ah*40;

    const float* bsrc = nullptr; uint32_t bdst = 0; int bc = 0;
    if (BTRANS){
        bsrc = B + (size_t)(bn + arow)*ldb + ah*10;
        bdst = smb + 10240 + arow*80 + ah*40;
    } else {
        const int bk = tid & 15; bc = (tid>>4)*(NI/2);
        bsrc = B + (size_t)bk*ldb + bn;
        bdst = smb + 10240 + (uint32_t)bk*(BPITCH*4);
    }

    auto ld = [&](int kt, int stg){
        const int k0 = kt*KT;
        const uint32_t so = stg*STG;
        {   const float* sa = asrc + k0;
            uint32_t d = adst + so;
            if (ah==0){ CP16(d,sa); CP16(d+16,sa+4); CP8(d+32,sa+8); }
            else      { CP8(d,sa); CP16(d+8,sa+2); CP16(d+24,sa+6); }
        }
        if (BTRANS){
            const float* sb = bsrc + k0;
            uint32_t d = bdst + so;
            if (ah==0){ CP16(d,sb); CP16(d+16,sb+4); CP8(d+32,sb+8); }
            else      { CP8(d,sb); CP16(d+8,sb+2); CP16(d+24,sb+6); }
        } else {
            const float* sb = bsrc + (size_t)k0*ldb;
            CP16(bdst + so + (uint32_t)(bc<<4), sb + bc*4);
            if (NI==4) CP16(bdst + so + (uint32_t)((bc+1)<<4), sb + (bc+1)*4);
        }
        CPCOMMIT();
    };

    const int nkt = K/KT;
#pragma unroll
    for (int p=0;p<STAGES-1;p++){ if (p<nkt) ld(p,p); else CPCOMMIT(); }

    for (int kt=0; kt<nkt; kt++){
        CPWAIT(STAGES-2);
        __syncthreads();
        const int nxt = kt + STAGES-1;
        if (nxt < nkt) ld(nxt, nxt%STAGES); else CPCOMMIT();
        const float* pA = (const float*)(sm + (kt%STAGES)*STG);
        const float* pB = (const float*)(sm + (kt%STAGES)*STG + 10240);
#pragma unroll
        for (int kk=0;kk<2;kk++){
            const int c0 = kk*8 + s, kr = kk*8 + s;
            uint32_t af[4][4];
#pragma unroll
            for (int im=0;im<4;im++){
                const int r0 = wm*64 + im*16 + q;
                af[im][0]=tf32cvt(pA[r0*20+c0]);     af[im][1]=tf32cvt(pA[(r0+8)*20+c0]);
                af[im][2]=tf32cvt(pA[r0*20+c0+4]);   af[im][3]=tf32cvt(pA[(r0+8)*20+c0+4]);
            }
#pragma unroll
            for (int in=0;in<NI;in++){
                const int nn = wn*(NI*8) + in*8 + q;
                uint32_t b0,b1;
                if (BTRANS){
                    b0=tf32cvt(pB[nn*20+kr]); b1=tf32cvt(pB[nn*20+kr+4]);
                } else {
                    const int off = kr*BPITCH + nn;
                    b0=tf32cvt(pB[off]); b1=tf32cvt(pB[off + 4*BPITCH]);
                }
#pragma unroll
                for (int im=0;im<4;im++) mma8(acc[im][in], af[im], b0, b1);
            }
        }
    }
}

#define EPI(NI, ...) { const int lane=threadIdx.x&31, warp=threadIdx.x>>5; \
    const int wm=warp>>2, wn=warp&3; \
    _Pragma("unroll") for(int im=0;im<4;im++){ \
    _Pragma("unroll") for(int in=0;in<NI;in++){ \
    _Pragma("unroll") for(int h=0;h<2;h++){ \
    _Pragma("unroll") for(int g2=0;g2<2;g2++){ \
        const int row_l = wm*64+im*16+(lane>>2)+h*8; \
        const int col_l = wn*(NI*8)+in*8+(lane&3)*2+g2; \
        const float val = acc[im][in][h*2+g2]; __VA_ARGS__ }}}}}

#define SM_NN4 (STAGES*(10240 + KT*(4*32+8)*4))
#define SM_NT  (STAGES*(10240 + 10240))
#define SM_NN2 (STAGES*(10240 + KT*(2*32+8)*4))

// ---- GEMM kernels ----
__global__ void __launch_bounds__(256,2) k_qkv(
    const float* __restrict__ qw, const float* __restrict__ qb,
    const float* __restrict__ kw, const float* __restrict__ kb,
    const float* __restrict__ vw, const float* __restrict__ vb)
{
    extern __shared__ char sm[];
    const int tile = blockIdx.x, rm = blockIdx.y*128;
    const float* W; const float* bias; float* out; int ldo, bn;
    if (tile<8)       { W=qw; bias=qb; out=g_q; ldo=1024; bn=tile*128; }
    else if (tile<10) { W=kw; bias=kb; out=g_k; ldo=256;  bn=(tile-8)*128; }
    else              { W=vw; bias=vb; out=g_v; ldo=256;  bn=(tile-10)*128; }
    float acc[4][4][4];
    tc_loop<4,false,false>(acc, g_h, HD, nullptr, rm, W, ldo, bn, HD, sm);
    EPI(4, out[(size_t)(rm+row_l)*ldo + bn+col_l] = val + bias[bn+col_l]; )
}

__global__ void __launch_bounds__(256,2) k_scores()
{
    extern __shared__ char sm[];
    const int bh = blockIdx.z, b = bh>>4, h = bh&15, hk = h>>2;
    const int rm = blockIdx.y*128, bn = blockIdx.x*128;
    const float* Q  = g_q + (size_t)b*SEQ*1024 + h*64;
    const float* Kp = g_k + (size_t)b*SEQ*256 + hk*64;
    float acc[4][4][4];
    tc_loop<4,true,false>(acc, Q, 1024, nullptr, rm, Kp, 256, bn, 64, sm);
    float* o = g_sc + ((size_t)bh*SEQ + rm)*SEQ + bn;
    EPI(4, o[(size_t)row_l*SEQ + col_l] = val*0.125f; )
}

__global__ void __launch_bounds__(256,2) k_pv()
{
    extern __shared__ char sm[];
    const int bh = blockIdx.y, b = bh>>4, h = bh&15, hk = h>>2;
    const int rm = blockIdx.x*128;
    const float* P = g_sc + (size_t)bh*SEQ*SEQ;
    const float* V = g_v + (size_t)b*SEQ*256 + hk*64;
    float acc[4][2][4];
    tc_loop<2,false,false>(acc, P, SEQ, nullptr, rm, V, 256, 0, SEQ, sm);
    float* o = g_ao + (size_t)(b*SEQ + rm)*1024 + h*64;
    EPI(2, o[(size_t)row_l*1024 + col_l] = val; )
}

__global__ void __launch_bounds__(256,2) k_oproj(
    const float* __restrict__ ow, const float* __restrict__ ob,
    const float* __restrict__ x)
{
    extern __shared__ char sm[];
    const int bn = blockIdx.x*128, rm = blockIdx.y*128;
    float acc[4][4][4];
    tc_loop<4,false,false>(acc, g_ao, 1024, nullptr, rm, ow, HD, bn, 1024, sm);
    EPI(4, { const int r = rm+row_l; const int c = bn+col_l;
             g_x2[(size_t)r*HD + c] = val + ob[c] + x[(size_t)r*HD + c]; } )
}

__global__ void __launch_bounds__(256,2) k_gu(const float* __restrict__ W, int which)
{
    const int e = blockIdx.z, cnt = g_cnt[e], rm = blockIdx.y*128;
    if (rm >= cnt) return;
    extern __shared__ char sm[];
    __shared__ int srow[128];
    if (threadIdx.x < 128){
        int rr = rm + threadIdx.x;
        srow[threadIdx.x] = (rr < cnt) ? g_rows[e*TB + rr] : 0;
    }
    __syncthreads();
    const int bn = blockIdx.x*128;
    float acc[4][4][4];
    tc_loop<4,false,true>(acc, g_t, HD, srow, 0, W + (size_t)e*HD*ID, ID, bn, HD, sm);
    float* out = which ? g_act : g_gt;
    EPI(4, { const int r = rm+row_l;
             if (r < cnt) out[((size_t)e*TB + r)*ID + bn+col_l] = val; } )
}

__global__ void __launch_bounds__(256,2) k_down(const float* __restrict__ dw,
                                                const float* __restrict__ db)
{
    const int e = blockIdx.z, cnt = g_cnt[e], rm = blockIdx.y*128;
    if (rm >= cnt) return;
    extern __shared__ char sm[];
    const int bn = blockIdx.x*128;
    float acc[4][4][4];
    tc_loop<4,false,false>(acc, g_act + (size_t)e*TB*ID, ID, nullptr, rm,
                           dw + (size_t)e*ID*HD, HD, bn, ID, sm);
    EPI(4, { const int r = rm+row_l; const int c = bn+col_l;
             if (r < cnt) g_dn[((size_t)e*TB + r)*HD + c] = val + db[(size_t)e*HD + c]; } )
}

// ---- elementwise / small kernels ----
__device__ __forceinline__ void rms_body(const float* __restrict__ x,
    const float* __restrict__ w, float* __restrict__ o)
{
    const int t = blockIdx.x, tid = threadIdx.x;
    const float* xr = x + (size_t)t*HD;
    float s = 0.f;
    for (int i = tid; i < HD; i += 256){ float v = xr[i]; s += v*v; }
    __shared__ float red[256];
    red[tid] = s; __syncthreads();
    for (int st = 128; st > 0; st >>= 1){ if (tid < st) red[tid] += red[tid+st]; __syncthreads(); }
    const float inv = rsqrtf(red[0]*(1.f/1024.f) + 1.1920929e-07f);
    for (int i = tid; i < HD; i += 256)
        o[(size_t)t*HD + i] = xr[i]*inv*w[i];
}
__global__ void __launch_bounds__(256) k_rms1(const float* x, const float* w){ rms_body(x, w, g_h); }
__global__ void __launch_bounds__(256) k_rms2(const float* w){ rms_body(g_x2, w, g_t); }

__global__ void __launch_bounds__(256) k_softmax()
{
    const int row = blockIdx.x*8 + (threadIdx.x>>5), lane = threadIdx.x&31;
    float4* p = (float4*)(g_sc + (size_t)row*SEQ);
    float4 v[4]; float mx = -3.402823e38f;
#pragma unroll
    for (int i=0;i<4;i++){ v[i]=p[lane+32*i];
        mx = fmaxf(mx, fmaxf(fmaxf(v[i].x,v[i].y), fmaxf(v[i].z,v[i].w))); }
#pragma unroll
    for (int o=16;o>0;o>>=1) mx = fmaxf(mx, __shfl_xor_sync(~0u, mx, o));
    float sum = 0.f;
#pragma unroll
    for (int i=0;i<4;i++){
        v[i].x=__expf(v[i].x-mx); v[i].y=__expf(v[i].y-mx);
        v[i].z=__expf(v[i].z-mx); v[i].w=__expf(v[i].w-mx);
        sum += v[i].x+v[i].y+v[i].z+v[i].w; }
#pragma unroll
    for (int o=16;o>0;o>>=1) sum += __shfl_xor_sync(~0u, sum, o);
    const float inv = 1.f/sum;
#pragma unroll
    for (int i=0;i<4;i++){ v[i].x*=inv; v[i].y*=inv; v[i].z*=inv; v[i].w*=inv; p[lane+32*i]=v[i]; }
}

__global__ void k_zero(){ if (threadIdx.x < NE) g_cnt[threadIdx.x] = 0; }

__global__ void __launch_bounds__(256) k_router(const float* __restrict__ rw,
    const float* __restrict__ rb)
{
    const int t = blockIdx.x, tid = threadIdx.x;
    const float* x = g_t + (size_t)t*HD;
    const int e = tid & 7, ch = tid >> 3;
    float s = 0.f;
    for (int i = ch*32; i < ch*32+32; i++) s += x[i]*rw[i*NE + e];
    __shared__ float part[32][9];
    __shared__ float sl[8];
    part[ch][e] = s; __syncthreads();
    if (tid < 8){
        float l = rb[tid];
        for (int c2 = 0; c2 < 32; c2++) l += part[c2][tid];
        sl[tid] = l;
    }
    __syncthreads();
    if (tid == 0){
        int e0 = 0; float v0 = sl[0];
        for (int i = 1; i < 8; i++) if (sl[i] > v0){ v0 = sl[i]; e0 = i; }
        int e1 = -1; float v1 = -3.402823e38f;
        for (int i = 0; i < 8; i++){ if (i == e0) continue; if (sl[i] > v1){ v1 = sl[i]; e1 = i; } }
        const float z = __expf(v1 - v0);
        const float p0 = 1.f/(1.f+z), p1 = z/(1.f+z);
        const int r0 = atomicAdd(&g_cnt[e0], 1);
        const int r1 = atomicAdd(&g_cnt[e1], 1);
        g_rows[e0*TB + r0] = t; g_rows[e1*TB + r1] = t;
        g_se[t*2+0] = e0; g_sr[t*2+0] = r0; g_sp[t*2+0] = p0;
        g_se[t*2+1] = e1; g_sr[t*2+1] = r1; g_sp[t*2+1] = p1;
    }
}

__global__ void __launch_bounds__(256) k_silu(const float* __restrict__ gb,
    const float* __restrict__ ub)
{
    const int e = blockIdx.y, cnt = g_cnt[e], rm = blockIdx.x*128;
    if (rm >= cnt) return;
    const int tid = threadIdx.x;
    const int rend = min(cnt - rm, 128);
    for (int rr = 0; rr < rend; rr++){
        const size_t ro = ((size_t)e*TB + rm + rr)*ID;
        for (int c4 = tid; c4 < ID/4; c4 += 256){
            const int c = c4*4;
            float4 g = *(const float4*)(g_gt + ro + c);
            float4 u = *(const float4*)(g_act + ro + c);
            float4 bg = *(const float4*)(gb + (size_t)e*ID + c);
            float4 bu = *(const float4*)(ub + (size_t)e*ID + c);
            float gx=g.x+bg.x, gy=g.y+bg.y, gz=g.z+bg.z, gw=g.w+bg.w;
            float4 o;
            o.x = (gx/(1.f+__expf(-gx)))*(u.x+bu.x);
            o.y = (gy/(1.f+__expf(-gy)))*(u.y+bu.y);
            o.z = (gz/(1.f+__expf(-gz)))*(u.z+bu.z);
            o.w = (gw/(1.f+__expf(-gw)))*(u.w+bu.w);
            *(float4*)(g_act + ro + c) = o;
        }
    }
}

__global__ void __launch_bounds__(256) k_combine(float* __restrict__ out)
{
    const int t = blockIdx.x, tid = threadIdx.x;
    const int e0 = g_se[t*2+0], r0 = g_sr[t*2+0];
    const int e1 = g_se[t*2+1], r1 = g_sr[t*2+1];
    const float p0 = g_sp[t*2+0], p1 = g_sp[t*2+1];
    const float* d0 = g_dn + ((size_t)e0*TB + r0)*HD;
    const float* d1 = g_dn + ((size_t)e1*TB + r1)*HD;
    const float* xr = g_x2 + (size_t)t*HD;
    for (int i = tid; i < HD; i += 256)
        out[(size_t)t*HD + i] = xr[i] + p0*d0[i] + p1*d1[i];
}

// ---- launcher ----
extern "C" void kernel_launch(void* const* d_in, const int* in_sizes, int n_in,
                              void* d_out, int out_size)
{
    (void)in_sizes; (void)n_in; (void)out_size;
    const float* x   = (const float*)d_in[0];
    const float* n1w = (const float*)d_in[1];
    const float* qw  = (const float*)d_in[2];
    const float* qb  = (const float*)d_in[3];
    const float* kw  = (const float*)d_in[4];
    const float* kb  = (const float*)d_in[5];
    const float* vw  = (const float*)d_in[6];
    const float* vb  = (const float*)d_in[7];
    const float* ow  = (const float*)d_in[8];
    const float* ob  = (const float*)d_in[9];
    const float* n2w = (const float*)d_in[10];
    const float* rw  = (const float*)d_in[11];
    const float* rb  = (const float*)d_in[12];
    const float* gw  = (const float*)d_in[13];
    const float* gb  = (const float*)d_in[14];
    const float* uw  = (const float*)d_in[15];
    const float* ub  = (const float*)d_in[16];
    const float* dw  = (const float*)d_in[17];
    const float* db  = (const float*)d_in[18];
    float* out = (float*)d_out;

    cudaFuncSetAttribute(k_qkv,    cudaFuncAttributeMaxDynamicSharedMemorySize, SM_NN4);
    cudaFuncSetAttribute(k_scores, cudaFuncAttributeMaxDynamicSharedMemorySize, SM_NT);
    cudaFuncSetAttribute(k_pv,     cudaFuncAttributeMaxDynamicSharedMemorySize, SM_NN2);
    cudaFuncSetAttribute(k_oproj,  cudaFuncAttributeMaxDynamicSharedMemorySize, SM_NN4);
    cudaFuncSetAttribute(k_gu,     cudaFuncAttributeMaxDynamicSharedMemorySize, SM_NN4);
    cudaFuncSetAttribute(k_down,   cudaFuncAttributeMaxDynamicSharedMemorySize, SM_NN4);

    k_rms1<<<TB, 256>>>(x, n1w);
    k_qkv<<<dim3(12, 8), 256, SM_NN4>>>(qw, qb, kw, kb, vw, vb);
    k_scores<<<dim3(4, 4, NB*NHQ), 256, SM_NT>>>();
    k_softmax<<<NB*NHQ*SEQ/8, 256>>>();
    k_pv<<<dim3(4, NB*NHQ), 256, SM_NN2>>>();
    k_oproj<<<dim3(8, 8), 256, SM_NN4>>>(ow, ob, x);
    k_rms2<<<TB, 256>>>(n2w);
    k_zero<<<1, 32>>>();
    k_router<<<TB, 256>>>(rw, rb);
    k_gu<<<dim3(ID/128, 8, NE), 256, SM_NN4>>>(gw, 0);
    k_gu<<<dim3(ID/128, 8, NE), 256, SM_NN4>>>(uw, 1);
    k_silu<<<dim3(TB/128, NE), 256>>>(gb, ub);
    k_down<<<dim3(HD/128, 8, NE), 256, SM_NN4>>>(dw, db);
    k_combine<<<TB, 256>>>(out);
}

// round 7
// speedup vs baseline: 1.5147x; 1.5147x over previous
#include <cuda_runtime.h>
#include <math.h>
#include <stdint.h>

#define TB 1024
#define HD 1024
#define NHQ 16
#define NHKV 4
#define DH 64
#define SEQ 512
#define NB 2
#define NE 8
#define ID 4096

// ---- scratch ----
__device__ float g_h [TB*HD + 16];
__device__ float g_q [TB*NHQ*DH + 16];
__device__ float g_k [TB*NHKV*DH + 16];
__device__ float g_v [TB*NHKV*DH + 16];
__device__ float g_sc[(size_t)NB*NHQ*SEQ*SEQ + 16];
__device__ float g_ao[TB*NHQ*DH + 16];
__device__ float g_x2[TB*HD + 16];
__device__ float g_t [TB*HD + 16];
__device__ int   g_cnt[NE];
__device__ int   g_rows[NE*TB];
__device__ int   g_se[TB*2];
__device__ int   g_sr[TB*2];
__device__ float g_sp[TB*2];
__device__ float g_gt [(size_t)NE*TB*ID + 16];
__device__ float g_act[(size_t)NE*TB*ID + 16];
__device__ float g_dn [(size_t)NE*TB*HD + 16];

// ---- primitives ----
__device__ __forceinline__ uint32_t tf32cvt(float x){
    uint32_t u; asm("cvt.rna.tf32.f32 %0, %1;" : "=r"(u) : "f"(x)); return u;
}
__device__ __forceinline__ void mma8(float* d, const uint32_t* a, uint32_t b0, uint32_t b1){
    asm volatile("mma.sync.aligned.m16n8k8.row.col.f32.tf32.tf32.f32 "
        "{%0,%1,%2,%3},{%4,%5,%6,%7},{%8,%9},{%0,%1,%2,%3};"
        : "+f"(d[0]),"+f"(d[1]),"+f"(d[2]),"+f"(d[3])
        : "r"(a[0]),"r"(a[1]),"r"(a[2]),"r"(a[3]),"r"(b0),"r"(b1));
}

// ============ round-2-style tf32 MMA mainloop (templated) ============
// BM=128, BN=NI*32, k-step 16, register-staged double buffer, cvt at store.
// A smem: [128 rows][pitch 20].  B smem NN: [16 k][pitch NI*32+8].
// B smem NT (BTRANS): [128 n rows][pitch 20] (same layout as A).
template<int NI, bool BTRANS, bool GATHER>
__device__ __forceinline__ void mm_loop(float (&acc)[4][NI][4],
    const float* __restrict__ A, int lda, const int* srow, int rm,
    const float* __restrict__ B, int ldb, int bn, int K,
    uint32_t* As, uint32_t* Bs)
{
    const int BPITCH = BTRANS ? 20 : NI*32 + 8;
    const int ASTG = 128*20;
    const int BSTG = BTRANS ? 128*20 : 16*BPITCH;
    const int tid = threadIdx.x, lane = tid & 31, warp = tid >> 5;
    const int wm = warp >> 2, wn = warp & 3, q = lane >> 2, s = lane & 3;
#pragma unroll
    for (int i = 0; i < 4; i++)
#pragma unroll
        for (int j = 0; j < NI; j++)
#pragma unroll
            for (int r = 0; r < 4; r++) acc[i][j][r] = 0.f;

    const int f0 = tid, f1 = tid + 256;
    const int ar0 = f0 >> 2, ac0 = (f0 & 3) << 2;
    const int ar1 = f1 >> 2, ac1 = (f1 & 3) << 2;
    const int ga0 = GATHER ? srow[ar0] : rm + ar0;
    const int ga1 = GATHER ? srow[ar1] : rm + ar1;
    const float* pa0 = A + (size_t)ga0*lda + ac0;
    const float* pa1 = A + (size_t)ga1*lda + ac1;

    const float* pb0; const float* pb1 = nullptr;
    int bs0, bs1 = 0;
    if (BTRANS){
        pb0 = B + (size_t)(bn + ar0)*ldb + ac0;
        pb1 = B + (size_t)(bn + ar1)*ldb + ac1;
        bs0 = ar0*20 + ac0; bs1 = ar1*20 + ac1;
    } else if (NI == 4){
        const int bk0 = f0 >> 5, bc0 = (f0 & 31) << 2;
        const int bk1 = f1 >> 5, bc1 = (f1 & 31) << 2;
        pb0 = B + (size_t)bk0*ldb + bn + bc0;
        pb1 = B + (size_t)bk1*ldb + bn + bc1;
        bs0 = bk0*BPITCH + bc0; bs1 = bk1*BPITCH + bc1;
    } else { // NI==2: 16 rows x 64 cols, 1 float4 per thread
        const int bk0 = tid >> 4, bc0 = (tid & 15) << 2;
        pb0 = B + (size_t)bk0*ldb + bn + bc0;
        bs0 = bk0*BPITCH + bc0;
    }

    float4 va0, va1, vb0, vb1;
    auto gload = [&](int k0){
        va0 = *(const float4*)(pa0 + k0);
        va1 = *(const float4*)(pa1 + k0);
        if (BTRANS){
            vb0 = *(const float4*)(pb0 + k0);
            vb1 = *(const float4*)(pb1 + k0);
        } else {
            vb0 = *(const float4*)(pb0 + (size_t)k0*ldb);
            if (NI == 4) vb1 = *(const float4*)(pb1 + (size_t)k0*ldb);
        }
    };
    auto stage = [&](int buf){
        uint32_t* dA = As + buf*ASTG;
        dA[ar0*20+ac0+0]=tf32cvt(va0.x); dA[ar0*20+ac0+1]=tf32cvt(va0.y);
        dA[ar0*20+ac0+2]=tf32cvt(va0.z); dA[ar0*20+ac0+3]=tf32cvt(va0.w);
        dA[ar1*20+ac1+0]=tf32cvt(va1.x); dA[ar1*20+ac1+1]=tf32cvt(va1.y);
        dA[ar1*20+ac1+2]=tf32cvt(va1.z); dA[ar1*20+ac1+3]=tf32cvt(va1.w);
        uint32_t* dB = Bs + buf*BSTG;
        dB[bs0+0]=tf32cvt(vb0.x); dB[bs0+1]=tf32cvt(vb0.y);
        dB[bs0+2]=tf32cvt(vb0.z); dB[bs0+3]=tf32cvt(vb0.w);
        if (BTRANS || NI == 4){
            dB[bs1+0]=tf32cvt(vb1.x); dB[bs1+1]=tf32cvt(vb1.y);
            dB[bs1+2]=tf32cvt(vb1.z); dB[bs1+3]=tf32cvt(vb1.w);
        }
    };

    gload(0); stage(0); __syncthreads();
    const int nst = K >> 4;
    for (int st = 0; st < nst; st++){
        const int buf = st & 1;
        const bool more = (st + 1 < nst);
        if (more) gload((st + 1) << 4);
        const uint32_t* pA = As + buf*ASTG;
        const uint32_t* pB = Bs + buf*BSTG;
#pragma unroll
        for (int kk = 0; kk < 2; kk++){
            const int c0 = kk*8 + s;
            uint32_t af[4][4];
#pragma unroll
            for (int im = 0; im < 4; im++){
                const int r0 = wm*64 + im*16 + q;
                af[im][0]=pA[r0*20+c0];   af[im][1]=pA[(r0+8)*20+c0];
                af[im][2]=pA[r0*20+c0+4]; af[im][3]=pA[(r0+8)*20+c0+4];
            }
#pragma unroll
            for (int in = 0; in < NI; in++){
                const int nn = wn*(NI*8) + in*8 + q;
                uint32_t b0, b1;
                if (BTRANS){ b0 = pB[nn*20+c0]; b1 = pB[nn*20+c0+4]; }
                else       { b0 = pB[c0*BPITCH+nn]; b1 = pB[(c0+4)*BPITCH+nn]; }
#pragma unroll
                for (int im = 0; im < 4; im++) mma8(acc[im][in], af[im], b0, b1);
            }
        }
        if (more) stage(buf ^ 1);
        __syncthreads();
    }
}

#define EPI(NI, ...) { const int lane=threadIdx.x&31, warp=threadIdx.x>>5; \
    const int wm=warp>>2, wn=warp&3; \
    _Pragma("unroll") for(int im=0;im<4;im++){ \
    _Pragma("unroll") for(int in=0;in<NI;in++){ \
    _Pragma("unroll") for(int h=0;h<2;h++){ \
    _Pragma("unroll") for(int g2=0;g2<2;g2++){ \
        const int row_l = wm*64+im*16+(lane>>2)+h*8; \
        const int col_l = wn*(NI*8)+in*8+(lane&3)*2+g2; \
        const float val = acc[im][in][h*2+g2]; __VA_ARGS__ }}}}}

#define SMW_NN4 (2*(128*20) + 2*(16*136))
#define SMW_NT  (2*(128*20) + 2*(128*20))
#define SMW_NN2 (2*(128*20) + 2*(16*72))

// ---- GEMM kernels ----
__global__ void __launch_bounds__(256) k_qkv(
    const float* __restrict__ qw, const float* __restrict__ qb,
    const float* __restrict__ kw, const float* __restrict__ kb,
    const float* __restrict__ vw, const float* __restrict__ vb)
{
    __shared__ uint32_t sm[SMW_NN4];
    const int tile = blockIdx.x, rm = blockIdx.y*128;
    const float* W; const float* bias; float* out; int ldo, bn;
    if (tile<8)       { W=qw; bias=qb; out=g_q; ldo=1024; bn=tile*128; }
    else if (tile<10) { W=kw; bias=kb; out=g_k; ldo=256;  bn=(tile-8)*128; }
    else              { W=vw; bias=vb; out=g_v; ldo=256;  bn=(tile-10)*128; }
    float acc[4][4][4];
    mm_loop<4,false,false>(acc, g_h, HD, nullptr, rm, W, ldo, bn, HD, sm, sm + 2*(128*20));
    EPI(4, out[(size_t)(rm+row_l)*ldo + bn+col_l] = val + bias[bn+col_l]; )
}

__global__ void __launch_bounds__(256) k_scores()
{
    __shared__ uint32_t sm[SMW_NT];
    const int bh = blockIdx.z, b = bh>>4, h = bh&15, hk = h>>2;
    const int rm = blockIdx.y*128, bn = blockIdx.x*128;
    const float* Q  = g_q + (size_t)b*SEQ*1024 + h*64;
    const float* Kp = g_k + (size_t)b*SEQ*256 + hk*64;
    float acc[4][4][4];
    mm_loop<4,true,false>(acc, Q, 1024, nullptr, rm, Kp, 256, bn, 64, sm, sm + 2*(128*20));
    float* o = g_sc + ((size_t)bh*SEQ + rm)*SEQ + bn;
    EPI(4, o[(size_t)row_l*SEQ + col_l] = val*0.125f; )
}

__global__ void __launch_bounds__(256) k_pv()
{
    __shared__ uint32_t sm[SMW_NN2];
    const int bh = blockIdx.y, b = bh>>4, h = bh&15, hk = h>>2;
    const int rm = blockIdx.x*128;
    const float* P = g_sc + (size_t)bh*SEQ*SEQ;
    const float* V = g_v + (size_t)b*SEQ*256 + hk*64;
    float acc[4][2][4];
    mm_loop<2,false,false>(acc, P, SEQ, nullptr, rm, V, 256, 0, SEQ, sm, sm + 2*(128*20));
    float* o = g_ao + (size_t)(b*SEQ + rm)*1024 + h*64;
    EPI(2, o[(size_t)row_l*1024 + col_l] = val; )
}

__global__ void __launch_bounds__(256) k_oproj(
    const float* __restrict__ ow, const float* __restrict__ ob,
    const float* __restrict__ x)
{
    __shared__ uint32_t sm[SMW_NN4];
    const int bn = blockIdx.x*128, rm = blockIdx.y*128;
    float acc[4][4][4];
    mm_loop<4,false,false>(acc, g_ao, 1024, nullptr, rm, ow, HD, bn, 1024, sm, sm + 2*(128*20));
    EPI(4, { const int r = rm+row_l; const int c = bn+col_l;
             g_x2[(size_t)r*HD + c] = val + ob[c] + x[(size_t)r*HD + c]; } )
}

__global__ void __launch_bounds__(256) k_gu(const float* __restrict__ W, int which)
{
    const int e = blockIdx.z, cnt = g_cnt[e], rm = blockIdx.y*128;
    if (rm >= cnt) return;
    __shared__ uint32_t sm[SMW_NN4];
    __shared__ int srow[128];
    if (threadIdx.x < 128){
        int rr = rm + threadIdx.x;
        srow[threadIdx.x] = (rr < cnt) ? g_rows[e*TB + rr] : 0;
    }
    __syncthreads();
    const int bn = blockIdx.x*128;
    float acc[4][4][4];
    mm_loop<4,false,true>(acc, g_t, HD, srow, 0, W + (size_t)e*HD*ID, ID, bn, HD, sm, sm + 2*(128*20));
    float* out = which ? g_act : g_gt;
    EPI(4, { const int r = rm+row_l;
             if (r < cnt) out[((size_t)e*TB + r)*ID + bn+col_l] = val; } )
}

__global__ void __launch_bounds__(256) k_down(const float* __restrict__ dw,
                                              const float* __restrict__ db)
{
    const int e = blockIdx.z, cnt = g_cnt[e], rm = blockIdx.y*128;
    if (rm >= cnt) return;
    __shared__ uint32_t sm[SMW_NN4];
    const int bn = blockIdx.x*128;
    float acc[4][4][4];
    mm_loop<4,false,false>(acc, g_act + (size_t)e*TB*ID, ID, nullptr, rm,
                           dw + (size_t)e*ID*HD, HD, bn, ID, sm, sm + 2*(128*20));
    EPI(4, { const int r = rm+row_l; const int c = bn+col_l;
             if (r < cnt) g_dn[((size_t)e*TB + r)*HD + c] = val + db[(size_t)e*HD + c]; } )
}

// ---- elementwise / small kernels ----
__device__ __forceinline__ void rms_body(const float* __restrict__ x,
    const float* __restrict__ w, float* __restrict__ o)
{
    const int t = blockIdx.x, tid = threadIdx.x;
    const float* xr = x + (size_t)t*HD;
    float s = 0.f;
    for (int i = tid; i < HD; i += 256){ float v = xr[i]; s += v*v; }
    __shared__ float red[256];
    red[tid] = s; __syncthreads();
    for (int st = 128; st > 0; st >>= 1){ if (tid < st) red[tid] += red[tid+st]; __syncthreads(); }
    const float inv = rsqrtf(red[0]*(1.f/1024.f) + 1.1920929e-07f);
    for (int i = tid; i < HD; i += 256)
        o[(size_t)t*HD + i] = xr[i]*inv*w[i];
}
__global__ void __launch_bounds__(256) k_rms1(const float* x, const float* w){ rms_body(x, w, g_h); }
__global__ void __launch_bounds__(256) k_rms2(const float* w){ rms_body(g_x2, w, g_t); }

__global__ void __launch_bounds__(256) k_softmax()
{
    const int row = blockIdx.x*8 + (threadIdx.x>>5), lane = threadIdx.x&31;
    float4* p = (float4*)(g_sc + (size_t)row*SEQ);
    float4 v[4]; float mx = -3.402823e38f;
#pragma unroll
    for (int i=0;i<4;i++){ v[i]=p[lane+32*i];
        mx = fmaxf(mx, fmaxf(fmaxf(v[i].x,v[i].y), fmaxf(v[i].z,v[i].w))); }
#pragma unroll
    for (int o=16;o>0;o>>=1) mx = fmaxf(mx, __shfl_xor_sync(~0u, mx, o));
    float sum = 0.f;
#pragma unroll
    for (int i=0;i<4;i++){
        v[i].x=__expf(v[i].x-mx); v[i].y=__expf(v[i].y-mx);
        v[i].z=__expf(v[i].z-mx); v[i].w=__expf(v[i].w-mx);
        sum += v[i].x+v[i].y+v[i].z+v[i].w; }
#pragma unroll
    for (int o=16;o>0;o>>=1) sum += __shfl_xor_sync(~0u, sum, o);
    const float inv = 1.f/sum;
#pragma unroll
    for (int i=0;i<4;i++){ v[i].x*=inv; v[i].y*=inv; v[i].z*=inv; v[i].w*=inv; p[lane+32*i]=v[i]; }
}

__global__ void k_zero(){ if (threadIdx.x < NE) g_cnt[threadIdx.x] = 0; }

__global__ void __launch_bounds__(256) k_router(const float* __restrict__ rw,
    const float* __restrict__ rb)
{
    const int t = blockIdx.x, tid = threadIdx.x;
    const float* x = g_t + (size_t)t*HD;
    const int e = tid & 7, ch = tid >> 3;
    float s = 0.f;
    for (int i = ch*32; i < ch*32+32; i++) s += x[i]*rw[i*NE + e];
    __shared__ float part[32][9];
    __shared__ float sl[8];
    part[ch][e] = s; __syncthreads();
    if (tid < 8){
        float l = rb[tid];
        for (int c2 = 0; c2 < 32; c2++) l += part[c2][tid];
        sl[tid] = l;
    }
    __syncthreads();
    if (tid == 0){
        int e0 = 0; float v0 = sl[0];
        for (int i = 1; i < 8; i++) if (sl[i] > v0){ v0 = sl[i]; e0 = i; }
        int e1 = -1; float v1 = -3.402823e38f;
        for (int i = 0; i < 8; i++){ if (i == e0) continue; if (sl[i] > v1){ v1 = sl[i]; e1 = i; } }
        const float z = __expf(v1 - v0);
        const float p0 = 1.f/(1.f+z), p1 = z/(1.f+z);
        const int r0 = atomicAdd(&g_cnt[e0], 1);
        const int r1 = atomicAdd(&g_cnt[e1], 1);
        g_rows[e0*TB + r0] = t; g_rows[e1*TB + r1] = t;
        g_se[t*2+0] = e0; g_sr[t*2+0] = r0; g_sp[t*2+0] = p0;
        g_se[t*2+1] = e1; g_sr[t*2+1] = r1; g_sp[t*2+1] = p1;
    }
}

__global__ void __launch_bounds__(256) k_silu(const float* __restrict__ gb,
    const float* __restrict__ ub)
{
    const int e = blockIdx.y, cnt = g_cnt[e], rm = blockIdx.x*128;
    if (rm >= cnt) return;
    const int tid = threadIdx.x;
    const int rend = min(cnt - rm, 128);
    for (int rr = 0; rr < rend; rr++){
        const size_t ro = ((size_t)e*TB + rm + rr)*ID;
        for (int c4 = tid; c4 < ID/4; c4 += 256){
            const int c = c4*4;
            float4 g = *(const float4*)(g_gt + ro + c);
            float4 u = *(const float4*)(g_act + ro + c);
            float4 bg = *(const float4*)(gb + (size_t)e*ID + c);
            float4 bu = *(const float4*)(ub + (size_t)e*ID + c);
            float gx=g.x+bg.x, gy=g.y+bg.y, gz=g.z+bg.z, gw=g.w+bg.w;
            float4 o;
            o.x = (gx/(1.f+__expf(-gx)))*(u.x+bu.x);
            o.y = (gy/(1.f+__expf(-gy)))*(u.y+bu.y);
            o.z = (gz/(1.f+__expf(-gz)))*(u.z+bu.z);
            o.w = (gw/(1.f+__expf(-gw)))*(u.w+bu.w);
            *(float4*)(g_act + ro + c) = o;
        }
    }
}

__global__ void __launch_bounds__(256) k_combine(float* __restrict__ out)
{
    const int t = blockIdx.x, tid = threadIdx.x;
    const int e0 = g_se[t*2+0], r0 = g_sr[t*2+0];
    const int e1 = g_se[t*2+1], r1 = g_sr[t*2+1];
    const float p0 = g_sp[t*2+0], p1 = g_sp[t*2+1];
    const float* d0 = g_dn + ((size_t)e0*TB + r0)*HD;
    const float* d1 = g_dn + ((size_t)e1*TB + r1)*HD;
    const float* xr = g_x2 + (size_t)t*HD;
    for (int i = tid; i < HD; i += 256)
        out[(size_t)t*HD + i] = xr[i] + p0*d0[i] + p1*d1[i];
}

// ---- launcher ----
extern "C" void kernel_launch(void* const* d_in, const int* in_sizes, int n_in,
                              void* d_out, int out_size)
{
    (void)in_sizes; (void)n_in; (void)out_size;
    const float* x   = (const float*)d_in[0];
    const float* n1w = (const float*)d_in[1];
    const float* qw  = (const float*)d_in[2];
    const float* qb  = (const float*)d_in[3];
    const float* kw  = (const float*)d_in[4];
    const float* kb  = (const float*)d_in[5];
    const float* vw  = (const float*)d_in[6];
    const float* vb  = (const float*)d_in[7];
    const float* ow  = (const float*)d_in[8];
    const float* ob  = (const float*)d_in[9];
    const float* n2w = (const float*)d_in[10];
    const float* rw  = (const float*)d_in[11];
    const float* rb  = (const float*)d_in[12];
    const float* gw  = (const float*)d_in[13];
    const float* gb  = (const float*)d_in[14];
    const float* uw  = (const float*)d_in[15];
    const float* ub  = (const float*)d_in[16];
    const float* dw  = (const float*)d_in[17];
    const float* db  = (const float*)d_in[18];
    float* out = (float*)d_out;

    k_rms1<<<TB, 256>>>(x, n1w);
    k_qkv<<<dim3(12, 8), 256>>>(qw, qb, kw, kb, vw, vb);
    k_scores<<<dim3(4, 4, NB*NHQ), 256>>>();
    k_softmax<<<NB*NHQ*SEQ/8, 256>>>();
    k_pv<<<dim3(4, NB*NHQ), 256>>>();
    k_oproj<<<dim3(8, 8), 256>>>(ow, ob, x);
    k_rms2<<<TB, 256>>>(n2w);
    k_zero<<<1, 32>>>();
    k_router<<<TB, 256>>>(rw, rb);
    k_gu<<<dim3(ID/128, 8, NE), 256>>>(gw, 0);
    k_gu<<<dim3(ID/128, 8, NE), 256>>>(uw, 1);
    k_silu<<<dim3(TB/128, NE), 256>>>(gb, ub);
    k_down<<<dim3(HD/128, 8, NE), 256>>>(dw, db);
    k_combine<<<TB, 256>>>(out);
}

// round 8
// speedup vs baseline: 2.1736x; 1.4350x over previous
#include <cuda_runtime.h>
#include <math.h>
#include <stdint.h>

#define TB 1024
#define HD 1024
#define NHQ 16
#define NHKV 4
#define DH 64
#define SEQ 512
#define NB 2
#define NE 8
#define ID 4096

// ---- scratch ----
__device__ float g_h [TB*HD + 16];
__device__ float g_q [TB*NHQ*DH + 16];
__device__ float g_k [TB*NHKV*DH + 16];
__device__ float g_v [TB*NHKV*DH + 16];
__device__ float g_sc[(size_t)NB*NHQ*SEQ*SEQ + 16];
__device__ float g_ao[TB*NHQ*DH + 16];
__device__ float g_x2[TB*HD + 16];
__device__ float g_t [TB*HD + 16];
__device__ int   g_cnt[NE];
__device__ int   g_rows[NE*TB];
__device__ int   g_se[TB*2];
__device__ int   g_sr[TB*2];
__device__ float g_sp[TB*2];
__device__ float g_act[(size_t)NE*TB*ID + 16];
__device__ float g_dn [(size_t)NE*TB*HD + 16];

// ---- primitives ----
__device__ __forceinline__ uint32_t tf32cvt(float x){
    uint32_t u; asm("cvt.rna.tf32.f32 %0, %1;" : "=r"(u) : "f"(x)); return u;
}
__device__ __forceinline__ void mma8(float* d, const uint32_t* a, uint32_t b0, uint32_t b1){
    asm volatile("mma.sync.aligned.m16n8k8.row.col.f32.tf32.tf32.f32 "
        "{%0,%1,%2,%3},{%4,%5,%6,%7},{%8,%9},{%0,%1,%2,%3};"
        : "+f"(d[0]),"+f"(d[1]),"+f"(d[2]),"+f"(d[3])
        : "r"(a[0]),"r"(a[1]),"r"(a[2]),"r"(a[3]),"r"(b0),"r"(b1));
}

// ============ round-2-style tf32 MMA mainloop (templated) ============
template<int NI, bool BTRANS, bool GATHER>
__device__ __forceinline__ void mm_loop(float (&acc)[4][NI][4],
    const float* __restrict__ A, int lda, const int* srow, int rm,
    const float* __restrict__ B, int ldb, int bn, int K,
    uint32_t* As, uint32_t* Bs)
{
    const int BPITCH = BTRANS ? 20 : NI*32 + 8;
    const int ASTG = 128*20;
    const int BSTG = BTRANS ? 128*20 : 16*BPITCH;
    const int tid = threadIdx.x, lane = tid & 31, warp = tid >> 5;
    const int wm = warp >> 2, wn = warp & 3, q = lane >> 2, s = lane & 3;
#pragma unroll
    for (int i = 0; i < 4; i++)
#pragma unroll
        for (int j = 0; j < NI; j++)
#pragma unroll
            for (int r = 0; r < 4; r++) acc[i][j][r] = 0.f;

    const int f0 = tid, f1 = tid + 256;
    const int ar0 = f0 >> 2, ac0 = (f0 & 3) << 2;
    const int ar1 = f1 >> 2, ac1 = (f1 & 3) << 2;
    const int ga0 = GATHER ? srow[ar0] : rm + ar0;
    const int ga1 = GATHER ? srow[ar1] : rm + ar1;
    const float* pa0 = A + (size_t)ga0*lda + ac0;
    const float* pa1 = A + (size_t)ga1*lda + ac1;

    const float* pb0; const float* pb1 = nullptr;
    int bs0, bs1 = 0;
    if (BTRANS){
        pb0 = B + (size_t)(bn + ar0)*ldb + ac0;
        pb1 = B + (size_t)(bn + ar1)*ldb + ac1;
        bs0 = ar0*20 + ac0; bs1 = ar1*20 + ac1;
    } else if (NI == 4){
        const int bk0 = f0 >> 5, bc0 = (f0 & 31) << 2;
        const int bk1 = f1 >> 5, bc1 = (f1 & 31) << 2;
        pb0 = B + (size_t)bk0*ldb + bn + bc0;
        pb1 = B + (size_t)bk1*ldb + bn + bc1;
        bs0 = bk0*BPITCH + bc0; bs1 = bk1*BPITCH + bc1;
    } else {
        const int bk0 = tid >> 4, bc0 = (tid & 15) << 2;
        pb0 = B + (size_t)bk0*ldb + bn + bc0;
        bs0 = bk0*BPITCH + bc0;
    }

    float4 va0, va1, vb0, vb1;
    auto gload = [&](int k0){
        va0 = *(const float4*)(pa0 + k0);
        va1 = *(const float4*)(pa1 + k0);
        if (BTRANS){
            vb0 = *(const float4*)(pb0 + k0);
            vb1 = *(const float4*)(pb1 + k0);
        } else {
            vb0 = *(const float4*)(pb0 + (size_t)k0*ldb);
            if (NI == 4) vb1 = *(const float4*)(pb1 + (size_t)k0*ldb);
        }
    };
    auto stage = [&](int buf){
        uint32_t* dA = As + buf*ASTG;
        dA[ar0*20+ac0+0]=tf32cvt(va0.x); dA[ar0*20+ac0+1]=tf32cvt(va0.y);
        dA[ar0*20+ac0+2]=tf32cvt(va0.z); dA[ar0*20+ac0+3]=tf32cvt(va0.w);
        dA[ar1*20+ac1+0]=tf32cvt(va1.x); dA[ar1*20+ac1+1]=tf32cvt(va1.y);
        dA[ar1*20+ac1+2]=tf32cvt(va1.z); dA[ar1*20+ac1+3]=tf32cvt(va1.w);
        uint32_t* dB = Bs + buf*BSTG;
        dB[bs0+0]=tf32cvt(vb0.x); dB[bs0+1]=tf32cvt(vb0.y);
        dB[bs0+2]=tf32cvt(vb0.z); dB[bs0+3]=tf32cvt(vb0.w);
        if (BTRANS || NI == 4){
            dB[bs1+0]=tf32cvt(vb1.x); dB[bs1+1]=tf32cvt(vb1.y);
            dB[bs1+2]=tf32cvt(vb1.z); dB[bs1+3]=tf32cvt(vb1.w);
        }
    };

    gload(0); stage(0); __syncthreads();
    const int nst = K >> 4;
    for (int st = 0; st < nst; st++){
        const int buf = st & 1;
        const bool more = (st + 1 < nst);
        if (more) gload((st + 1) << 4);
        const uint32_t* pA = As + buf*ASTG;
        const uint32_t* pB = Bs + buf*BSTG;
#pragma unroll
        for (int kk = 0; kk < 2; kk++){
            const int c0 = kk*8 + s;
            uint32_t af[4][4];
#pragma unroll
            for (int im = 0; im < 4; im++){
                const int r0 = wm*64 + im*16 + q;
                af[im][0]=pA[r0*20+c0];   af[im][1]=pA[(r0+8)*20+c0];
                af[im][2]=pA[r0*20+c0+4]; af[im][3]=pA[(r0+8)*20+c0+4];
            }
#pragma unroll
            for (int in = 0; in < NI; in++){
                const int nn = wn*(NI*8) + in*8 + q;
                uint32_t b0, b1;
                if (BTRANS){ b0 = pB[nn*20+c0]; b1 = pB[nn*20+c0+4]; }
                else       { b0 = pB[c0*BPITCH+nn]; b1 = pB[(c0+4)*BPITCH+nn]; }
#pragma unroll
                for (int im = 0; im < 4; im++) mma8(acc[im][in], af[im], b0, b1);
            }
        }
        if (more) stage(buf ^ 1);
        __syncthreads();
    }
}

// ============ dual-B mainloop (fused gate+up), 256 thr, warp 64x32 ============
__device__ __forceinline__ void mm_dual(float (&a1)[4][4][4], float (&a2)[4][4][4],
    const float* __restrict__ A, int lda, const int* srow,
    const float* __restrict__ B1, const float* __restrict__ B2,
    int ldb, int bn, int K,
    uint32_t* As, uint32_t* B1s, uint32_t* B2s)
{
    const int ASTG = 128*20, BSTG = 16*136;
    const int tid = threadIdx.x, lane = tid & 31, warp = tid >> 5;
    const int wm = warp >> 2, wn = warp & 3, q = lane >> 2, s = lane & 3;
#pragma unroll
    for (int i = 0; i < 4; i++)
#pragma unroll
        for (int j = 0; j < 4; j++)
#pragma unroll
            for (int r = 0; r < 4; r++){ a1[i][j][r]=0.f; a2[i][j][r]=0.f; }

    const int f0 = tid, f1 = tid + 256;
    const int ar0 = f0 >> 2, ac0 = (f0 & 3) << 2;
    const int ar1 = f1 >> 2, ac1 = (f1 & 3) << 2;
    const float* pa0 = A + (size_t)srow[ar0]*lda + ac0;
    const float* pa1 = A + (size_t)srow[ar1]*lda + ac1;
    const int bk0 = f0 >> 5, bc0 = (f0 & 31) << 2;
    const int bk1 = f1 >> 5, bc1 = (f1 & 31) << 2;
    const int bs0 = bk0*136 + bc0, bs1 = bk1*136 + bc1;
    const float* p10 = B1 + (size_t)bk0*ldb + bn + bc0;
    const float* p11 = B1 + (size_t)bk1*ldb + bn + bc1;
    const float* p20 = B2 + (size_t)bk0*ldb + bn + bc0;
    const float* p21 = B2 + (size_t)bk1*ldb + bn + bc1;

    float4 va0, va1, w10, w11, w20, w21;
    auto gload = [&](int k0){
        va0 = *(const float4*)(pa0 + k0);
        va1 = *(const float4*)(pa1 + k0);
        w10 = *(const float4*)(p10 + (size_t)k0*ldb);
        w11 = *(const float4*)(p11 + (size_t)k0*ldb);
        w20 = *(const float4*)(p20 + (size_t)k0*ldb);
        w21 = *(const float4*)(p21 + (size_t)k0*ldb);
    };
    auto stage = [&](int buf){
        uint32_t* dA = As + buf*ASTG;
        dA[ar0*20+ac0+0]=tf32cvt(va0.x); dA[ar0*20+ac0+1]=tf32cvt(va0.y);
        dA[ar0*20+ac0+2]=tf32cvt(va0.z); dA[ar0*20+ac0+3]=tf32cvt(va0.w);
        dA[ar1*20+ac1+0]=tf32cvt(va1.x); dA[ar1*20+ac1+1]=tf32cvt(va1.y);
        dA[ar1*20+ac1+2]=tf32cvt(va1.z); dA[ar1*20+ac1+3]=tf32cvt(va1.w);
        uint32_t* d1 = B1s + buf*BSTG;
        d1[bs0+0]=tf32cvt(w10.x); d1[bs0+1]=tf32cvt(w10.y);
        d1[bs0+2]=tf32cvt(w10.z); d1[bs0+3]=tf32cvt(w10.w);
        d1[bs1+0]=tf32cvt(w11.x); d1[bs1+1]=tf32cvt(w11.y);
        d1[bs1+2]=tf32cvt(w11.z); d1[bs1+3]=tf32cvt(w11.w);
        uint32_t* d2 = B2s + buf*BSTG;
        d2[bs0+0]=tf32cvt(w20.x); d2[bs0+1]=tf32cvt(w20.y);
        d2[bs0+2]=tf32cvt(w20.z); d2[bs0+3]=tf32cvt(w20.w);
        d2[bs1+0]=tf32cvt(w21.x); d2[bs1+1]=tf32cvt(w21.y);
        d2[bs1+2]=tf32cvt(w21.z); d2[bs1+3]=tf32cvt(w21.w);
    };

    gload(0); stage(0); __syncthreads();
    const int nst = K >> 4;
    for (int st = 0; st < nst; st++){
        const int buf = st & 1;
        const bool more = (st + 1 < nst);
        if (more) gload((st + 1) << 4);
        const uint32_t* pA = As + buf*ASTG;
        const uint32_t* q1 = B1s + buf*BSTG;
        const uint32_t* q2 = B2s + buf*BSTG;
#pragma unroll
        for (int kk = 0; kk < 2; kk++){
            const int c0 = kk*8 + s;
            uint32_t af[4][4];
#pragma unroll
            for (int im = 0; im < 4; im++){
                const int r0 = wm*64 + im*16 + q;
                af[im][0]=pA[r0*20+c0];   af[im][1]=pA[(r0+8)*20+c0];
                af[im][2]=pA[r0*20+c0+4]; af[im][3]=pA[(r0+8)*20+c0+4];
            }
#pragma unroll
            for (int in = 0; in < 4; in++){
                const int nn = wn*32 + in*8 + q;
                uint32_t b0 = q1[c0*136+nn], b1 = q1[(c0+4)*136+nn];
                uint32_t c0b = q2[c0*136+nn], c1b = q2[(c0+4)*136+nn];
#pragma unroll
                for (int im = 0; im < 4; im++){
                    mma8(a1[im][in], af[im], b0, b1);
                    mma8(a2[im][in], af[im], c0b, c1b);
                }
            }
        }
        if (more) stage(buf ^ 1);
        __syncthreads();
    }
}

// ============ 4-warp (128 thr) warp-64x64 mainloop for k_down ============
__device__ __forceinline__ void mm_down(float (&acc)[4][8][4],
    const float* __restrict__ A, int lda, int rm,
    const float* __restrict__ B, int ldb, int bn, int K,
    uint32_t* As, uint32_t* Bs)
{
    const int ASTG = 128*20, BSTG = 16*136;
    const int tid = threadIdx.x, lane = tid & 31, warp = tid >> 5;
    const int wm = warp >> 1, wn = warp & 1, q = lane >> 2, s = lane & 3;
#pragma unroll
    for (int i = 0; i < 4; i++)
#pragma unroll
        for (int j = 0; j < 8; j++)
#pragma unroll
            for (int r = 0; r < 4; r++) acc[i][j][r] = 0.f;

    int ar[4], ac[4], bs[4];
    const float* pa[4]; const float* pb[4];
#pragma unroll
    for (int i = 0; i < 4; i++){
        const int f = tid + i*128;
        ar[i] = f >> 2; ac[i] = (f & 3) << 2;
        pa[i] = A + (size_t)(rm + ar[i])*lda + ac[i];
        const int bk = f >> 5, bc = (f & 31) << 2;
        bs[i] = bk*136 + bc;
        pb[i] = B + (size_t)bk*ldb + bn + bc;
    }

    float4 va[4], vb[4];
    auto gload = [&](int k0){
#pragma unroll
        for (int i = 0; i < 4; i++){
            va[i] = *(const float4*)(pa[i] + k0);
            vb[i] = *(const float4*)(pb[i] + (size_t)k0*ldb);
        }
    };
    auto stage = [&](int buf){
        uint32_t* dA = As + buf*ASTG;
        uint32_t* dB = Bs + buf*BSTG;
#pragma unroll
        for (int i = 0; i < 4; i++){
            const int o = ar[i]*20 + ac[i];
            dA[o+0]=tf32cvt(va[i].x); dA[o+1]=tf32cvt(va[i].y);
            dA[o+2]=tf32cvt(va[i].z); dA[o+3]=tf32cvt(va[i].w);
            dB[bs[i]+0]=tf32cvt(vb[i].x); dB[bs[i]+1]=tf32cvt(vb[i].y);
            dB[bs[i]+2]=tf32cvt(vb[i].z); dB[bs[i]+3]=tf32cvt(vb[i].w);
        }
    };

    gload(0); stage(0); __syncthreads();
    const int nst = K >> 4;
    for (int st = 0; st < nst; st++){
        const int buf = st & 1;
        const bool more = (st + 1 < nst);
        if (more) gload((st + 1) << 4);
        const uint32_t* pA = As + buf*ASTG;
        const uint32_t* pB = Bs + buf*BSTG;
#pragma unroll
        for (int kk = 0; kk < 2; kk++){
            const int c0 = kk*8 + s;
            uint32_t af[4][4];
#pragma unroll
            for (int im = 0; im < 4; im++){
                const int r0 = wm*64 + im*16 + q;
                af[im][0]=pA[r0*20+c0];   af[im][1]=pA[(r0+8)*20+c0];
                af[im][2]=pA[r0*20+c0+4]; af[im][3]=pA[(r0+8)*20+c0+4];
            }
#pragma unroll
            for (int in = 0; in < 8; in++){
                const int nn = wn*64 + in*8 + q;
                uint32_t b0 = pB[c0*136+nn], b1 = pB[(c0+4)*136+nn];
#pragma unroll
                for (int im = 0; im < 4; im++) mma8(acc[im][in], af[im], b0, b1);
            }
        }
        if (more) stage(buf ^ 1);
        __syncthreads();
    }
}

#define EPI(NI, ...) { const int lane=threadIdx.x&31, warp=threadIdx.x>>5; \
    const int wm=warp>>2, wn=warp&3; \
    _Pragma("unroll") for(int im=0;im<4;im++){ \
    _Pragma("unroll") for(int in=0;in<NI;in++){ \
    _Pragma("unroll") for(int h=0;h<2;h++){ \
    _Pragma("unroll") for(int g2=0;g2<2;g2++){ \
        const int row_l = wm*64+im*16+(lane>>2)+h*8; \
        const int col_l = wn*(NI*8)+in*8+(lane&3)*2+g2; \
        const float val = acc[im][in][h*2+g2]; __VA_ARGS__ }}}}}

#define SMW_NN4 (2*(128*20) + 2*(16*136))
#define SMW_NT  (2*(128*20) + 2*(128*20))
#define SMW_NN2 (2*(128*20) + 2*(16*72))
#define SMB_GUF ((2*(128*20) + 4*(16*136))*4)

// ---- GEMM kernels ----
__global__ void __launch_bounds__(256) k_qkv(
    const float* __restrict__ qw, const float* __restrict__ qb,
    const float* __restrict__ kw, const float* __restrict__ kb,
    const float* __restrict__ vw, const float* __restrict__ vb)
{
    __shared__ uint32_t sm[SMW_NN4];
    const int tile = blockIdx.x, rm = blockIdx.y*128;
    const float* W; const float* bias; float* out; int ldo, bn;
    if (tile<8)       { W=qw; bias=qb; out=g_q; ldo=1024; bn=tile*128; }
    else if (tile<10) { W=kw; bias=kb; out=g_k; ldo=256;  bn=(tile-8)*128; }
    else              { W=vw; bias=vb; out=g_v; ldo=256;  bn=(tile-10)*128; }
    float acc[4][4][4];
    mm_loop<4,false,false>(acc, g_h, HD, nullptr, rm, W, ldo, bn, HD, sm, sm + 2*(128*20));
    EPI(4, out[(size_t)(rm+row_l)*ldo + bn+col_l] = val + bias[bn+col_l]; )
}

__global__ void __launch_bounds__(256) k_scores()
{
    __shared__ uint32_t sm[SMW_NT];
    const int bh = blockIdx.z, b = bh>>4, h = bh&15, hk = h>>2;
    const int rm = blockIdx.y*128, bn = blockIdx.x*128;
    const float* Q  = g_q + (size_t)b*SEQ*1024 + h*64;
    const float* Kp = g_k + (size_t)b*SEQ*256 + hk*64;
    float acc[4][4][4];
    mm_loop<4,true,false>(acc, Q, 1024, nullptr, rm, Kp, 256, bn, 64, sm, sm + 2*(128*20));
    float* o = g_sc + ((size_t)bh*SEQ + rm)*SEQ + bn;
    EPI(4, o[(size_t)row_l*SEQ + col_l] = val*0.125f; )
}

__global__ void __launch_bounds__(256) k_pv()
{
    __shared__ uint32_t sm[SMW_NN2];
    const int bh = blockIdx.y, b = bh>>4, h = bh&15, hk = h>>2;
    const int rm = blockIdx.x*128;
    const float* P = g_sc + (size_t)bh*SEQ*SEQ;
    const float* V = g_v + (size_t)b*SEQ*256 + hk*64;
    float acc[4][2][4];
    mm_loop<2,false,false>(acc, P, SEQ, nullptr, rm, V, 256, 0, SEQ, sm, sm + 2*(128*20));
    float* o = g_ao + (size_t)(b*SEQ + rm)*1024 + h*64;
    EPI(2, o[(size_t)row_l*1024 + col_l] = val; )
}

__global__ void __launch_bounds__(256) k_oproj(
    const float* __restrict__ ow, const float* __restrict__ ob,
    const float* __restrict__ x)
{
    __shared__ uint32_t sm[SMW_NN4];
    const int bn = blockIdx.x*128, rm = blockIdx.y*128;
    float acc[4][4][4];
    mm_loop<4,false,false>(acc, g_ao, 1024, nullptr, rm, ow, HD, bn, 1024, sm, sm + 2*(128*20));
    EPI(4, { const int r = rm+row_l; const int c = bn+col_l;
             g_x2[(size_t)r*HD + c] = val + ob[c] + x[(size_t)r*HD + c]; } )
}

// fused gate+up with silu epilogue
__global__ void __launch_bounds__(256) k_guf(
    const float* __restrict__ gw, const float* __restrict__ uw,
    const float* __restrict__ gb, const float* __restrict__ ub)
{
    const int e = blockIdx.z, cnt = g_cnt[e], rm = blockIdx.y*128;
    if (rm >= cnt) return;
    extern __shared__ uint32_t smg[];
    uint32_t* As = smg;
    uint32_t* B1 = smg + 2*(128*20);
    uint32_t* B2 = B1 + 2*(16*136);
    __shared__ int srow[128];
    if (threadIdx.x < 128){
        int rr = rm + threadIdx.x;
        srow[threadIdx.x] = (rr < cnt) ? g_rows[e*TB + rr] : 0;
    }
    __syncthreads();
    const int bn = blockIdx.x*128;
    float a1[4][4][4], a2[4][4][4];
    mm_dual(a1, a2, g_t, HD, srow,
            gw + (size_t)e*HD*ID, uw + (size_t)e*HD*ID, ID, bn, HD, As, B1, B2);
    {
        const int lane = threadIdx.x&31, warp = threadIdx.x>>5;
        const int wm = warp>>2, wn = warp&3;
#pragma unroll
        for (int im = 0; im < 4; im++)
#pragma unroll
            for (int in = 0; in < 4; in++)
#pragma unroll
                for (int h = 0; h < 2; h++)
#pragma unroll
                    for (int g2 = 0; g2 < 2; g2++){
                        const int r = rm + wm*64+im*16+(lane>>2)+h*8;
                        if (r >= cnt) continue;
                        const int c = bn + wn*32+in*8+(lane&3)*2+g2;
                        float g = a1[im][in][h*2+g2] + gb[(size_t)e*ID + c];
                        float u = a2[im][in][h*2+g2] + ub[(size_t)e*ID + c];
                        g_act[((size_t)e*TB + r)*ID + c] = (g/(1.f+__expf(-g)))*u;
                    }
    }
}

__global__ void __launch_bounds__(128) k_down(const float* __restrict__ dw,
                                              const float* __restrict__ db)
{
    const int e = blockIdx.z, cnt = g_cnt[e], rm = blockIdx.y*128;
    if (rm >= cnt) return;
    __shared__ uint32_t sm[SMW_NN4];
    const int bn = blockIdx.x*128;
    float acc[4][8][4];
    mm_down(acc, g_act + (size_t)e*TB*ID, ID, rm,
            dw + (size_t)e*ID*HD, HD, bn, ID, sm, sm + 2*(128*20));
    {
        const int lane = threadIdx.x&31, warp = threadIdx.x>>5;
        const int wm = warp>>1, wn = warp&1;
#pragma unroll
        for (int im = 0; im < 4; im++)
#pragma unroll
            for (int in = 0; in < 8; in++)
#pragma unroll
                for (int h = 0; h < 2; h++)
#pragma unroll
                    for (int g2 = 0; g2 < 2; g2++){
                        const int r = rm + wm*64+im*16+(lane>>2)+h*8;
                        if (r >= cnt) continue;
                        const int c = bn + wn*64+in*8+(lane&3)*2+g2;
                        g_dn[((size_t)e*TB + r)*HD + c] =
                            acc[im][in][h*2+g2] + db[(size_t)e*HD + c];
                    }
    }
}

// ---- elementwise / small kernels ----
__device__ __forceinline__ void rms_body(const float* __restrict__ x,
    const float* __restrict__ w, float* __restrict__ o)
{
    const int t = blockIdx.x, tid = threadIdx.x;
    const float* xr = x + (size_t)t*HD;
    float s = 0.f;
    for (int i = tid; i < HD; i += 256){ float v = xr[i]; s += v*v; }
    __shared__ float red[256];
    red[tid] = s; __syncthreads();
    for (int st = 128; st > 0; st >>= 1){ if (tid < st) red[tid] += red[tid+st]; __syncthreads(); }
    const float inv = rsqrtf(red[0]*(1.f/1024.f) + 1.1920929e-07f);
    for (int i = tid; i < HD; i += 256)
        o[(size_t)t*HD + i] = xr[i]*inv*w[i];
}
__global__ void __launch_bounds__(256) k_rms1(const float* x, const float* w){ rms_body(x, w, g_h); }
__global__ void __launch_bounds__(256) k_rms2(const float* w){ rms_body(g_x2, w, g_t); }

__global__ void __launch_bounds__(256) k_softmax()
{
    const int row = blockIdx.x*8 + (threadIdx.x>>5), lane = threadIdx.x&31;
    float4* p = (float4*)(g_sc + (size_t)row*SEQ);
    float4 v[4]; float mx = -3.402823e38f;
#pragma unroll
    for (int i=0;i<4;i++){ v[i]=p[lane+32*i];
        mx = fmaxf(mx, fmaxf(fmaxf(v[i].x,v[i].y), fmaxf(v[i].z,v[i].w))); }
#pragma unroll
    for (int o=16;o>0;o>>=1) mx = fmaxf(mx, __shfl_xor_sync(~0u, mx, o));
    float sum = 0.f;
#pragma unroll
    for (int i=0;i<4;i++){
        v[i].x=__expf(v[i].x-mx); v[i].y=__expf(v[i].y-mx);
        v[i].z=__expf(v[i].z-mx); v[i].w=__expf(v[i].w-mx);
        sum += v[i].x+v[i].y+v[i].z+v[i].w; }
#pragma unroll
    for (int o=16;o>0;o>>=1) sum += __shfl_xor_sync(~0u, sum, o);
    const float inv = 1.f/sum;
#pragma unroll
    for (int i=0;i<4;i++){ v[i].x*=inv; v[i].y*=inv; v[i].z*=inv; v[i].w*=inv; p[lane+32*i]=v[i]; }
}

__global__ void k_zero(){ if (threadIdx.x < NE) g_cnt[threadIdx.x] = 0; }

__global__ void __launch_bounds__(256) k_router(const float* __restrict__ rw,
    const float* __restrict__ rb)
{
    const int t = blockIdx.x, tid = threadIdx.x;
    const float* x = g_t + (size_t)t*HD;
    const int e = tid & 7, ch = tid >> 3;
    float s = 0.f;
    for (int i = ch*32; i < ch*32+32; i++) s += x[i]*rw[i*NE + e];
    __shared__ float part[32][9];
    __shared__ float sl[8];
    part[ch][e] = s; __syncthreads();
    if (tid < 8){
        float l = rb[tid];
        for (int c2 = 0; c2 < 32; c2++) l += part[c2][tid];
        sl[tid] = l;
    }
    __syncthreads();
    if (tid == 0){
        int e0 = 0; float v0 = sl[0];
        for (int i = 1; i < 8; i++) if (sl[i] > v0){ v0 = sl[i]; e0 = i; }
        int e1 = -1; float v1 = -3.402823e38f;
        for (int i = 0; i < 8; i++){ if (i == e0) continue; if (sl[i] > v1){ v1 = sl[i]; e1 = i; } }
        const float z = __expf(v1 - v0);
        const float p0 = 1.f/(1.f+z), p1 = z/(1.f+z);
        const int r0 = atomicAdd(&g_cnt[e0], 1);
        const int r1 = atomicAdd(&g_cnt[e1], 1);
        g_rows[e0*TB + r0] = t; g_rows[e1*TB + r1] = t;
        g_se[t*2+0] = e0; g_sr[t*2+0] = r0; g_sp[t*2+0] = p0;
        g_se[t*2+1] = e1; g_sr[t*2+1] = r1; g_sp[t*2+1] = p1;
    }
}

__global__ void __launch_bounds__(256) k_combine(float* __restrict__ out)
{
    const int t = blockIdx.x, tid = threadIdx.x;
    const int e0 = g_se[t*2+0], r0 = g_sr[t*2+0];
    const int e1 = g_se[t*2+1], r1 = g_sr[t*2+1];
    const float p0 = g_sp[t*2+0], p1 = g_sp[t*2+1];
    const float* d0 = g_dn + ((size_t)e0*TB + r0)*HD;
    const float* d1 = g_dn + ((size_t)e1*TB + r1)*HD;
    const float* xr = g_x2 + (size_t)t*HD;
    for (int i = tid; i < HD; i += 256)
        out[(size_t)t*HD + i] = xr[i] + p0*d0[i] + p1*d1[i];
}

// ---- launcher ----
extern "C" void kernel_launch(void* const* d_in, const int* in_sizes, int n_in,
                              void* d_out, int out_size)
{
    (void)in_sizes; (void)n_in; (void)out_size;
    const float* x   = (const float*)d_in[0];
    const float* n1w = (const float*)d_in[1];
    const float* qw  = (const float*)d_in[2];
    const float* qb  = (const float*)d_in[3];
    const float* kw  = (const float*)d_in[4];
    const float* kb  = (const float*)d_in[5];
    const float* vw  = (const float*)d_in[6];
    const float* vb  = (const float*)d_in[7];
    const float* ow  = (const float*)d_in[8];
    const float* ob  = (const float*)d_in[9];
    const float* n2w = (const float*)d_in[10];
    const float* rw  = (const float*)d_in[11];
    const float* rb  = (const float*)d_in[12];
    const float* gw  = (const float*)d_in[13];
    const float* gb  = (const float*)d_in[14];
    const float* uw  = (const float*)d_in[15];
    const float* ub  = (const float*)d_in[16];
    const float* dw  = (const float*)d_in[17];
    const float* db  = (const float*)d_in[18];
    float* out = (float*)d_out;

    cudaFuncSetAttribute(k_guf, cudaFuncAttributeMaxDynamicSharedMemorySize, SMB_GUF);

    k_rms1<<<TB, 256>>>(x, n1w);
    k_qkv<<<dim3(12, 8), 256>>>(qw, qb, kw, kb, vw, vb);
    k_scores<<<dim3(4, 4, NB*NHQ), 256>>>();
    k_softmax<<<NB*NHQ*SEQ/8, 256>>>();
    k_pv<<<dim3(4, NB*NHQ), 256>>>();
    k_oproj<<<dim3(8, 8), 256>>>(ow, ob, x);
    k_rms2<<<TB, 256>>>(n2w);
    k_zero<<<1, 32>>>();
    k_router<<<TB, 256>>>(rw, rb);
    k_guf<<<dim3(ID/128, 8, NE), 256, SMB_GUF>>>(gw, uw, gb, ub);
    k_down<<<dim3(HD/128, 8, NE), 128>>>(dw, db);
    k_combine<<<TB, 256>>>(out);
}

// round 9
// speedup vs baseline: 2.1827x; 1.0042x over previous
#include <cuda_runtime.h>
#include <math.h>
#include <stdint.h>

#define TB 1024
#define HD 1024
#define NHQ 16
#define NHKV 4
#define DH 64
#define SEQ 512
#define NB 2
#define NE 8
#define ID 4096

// ---- scratch ----
__device__ float g_h [TB*HD + 16];
__device__ float g_q [TB*NHQ*DH + 16];
__device__ float g_k [TB*NHKV*DH + 16];
__device__ float g_v [TB*NHKV*DH + 16];
__device__ float g_sc[(size_t)NB*NHQ*SEQ*SEQ + 16];
__device__ float g_ao[TB*NHQ*DH + 16];
__device__ float g_x2[TB*HD + 16];
__device__ float g_t [TB*HD + 16];
__device__ int   g_cnt[NE];
__device__ int   g_rows[NE*TB];
__device__ int   g_se[TB*2];
__device__ int   g_sr[TB*2];
__device__ float g_sp[TB*2];
__device__ float g_act[(size_t)NE*TB*ID + 16];
__device__ float g_dn [(size_t)NE*TB*HD + 16];

// ---- primitives ----
__device__ __forceinline__ uint32_t tf32cvt(float x){
    uint32_t u; asm("cvt.rna.tf32.f32 %0, %1;" : "=r"(u) : "f"(x)); return u;
}
__device__ __forceinline__ uint4 cvt4(float4 v){
    return make_uint4(tf32cvt(v.x), tf32cvt(v.y), tf32cvt(v.z), tf32cvt(v.w));
}
__device__ __forceinline__ void mma8(float* d, const uint32_t* a, uint32_t b0, uint32_t b1){
    asm volatile("mma.sync.aligned.m16n8k8.row.col.f32.tf32.tf32.f32 "
        "{%0,%1,%2,%3},{%4,%5,%6,%7},{%8,%9},{%0,%1,%2,%3};"
        : "+f"(d[0]),"+f"(d[1]),"+f"(d[2]),"+f"(d[3])
        : "r"(a[0]),"r"(a[1]),"r"(a[2]),"r"(a[3]),"r"(b0),"r"(b1));
}

// ============ tf32 MMA mainloop (templated), uint4 staging ============
template<int NI, bool BTRANS, bool GATHER>
__device__ __forceinline__ void mm_loop(float (&acc)[4][NI][4],
    const float* __restrict__ A, int lda, const int* srow, int rm,
    const float* __restrict__ B, int ldb, int bn, int K,
    uint32_t* As, uint32_t* Bs)
{
    const int BPITCH = BTRANS ? 20 : NI*32 + 8;
    const int ASTG = 128*20;
    const int BSTG = BTRANS ? 128*20 : 16*BPITCH;
    const int tid = threadIdx.x, lane = tid & 31, warp = tid >> 5;
    const int wm = warp >> 2, wn = warp & 3, q = lane >> 2, s = lane & 3;
#pragma unroll
    for (int i = 0; i < 4; i++)
#pragma unroll
        for (int j = 0; j < NI; j++)
#pragma unroll
            for (int r = 0; r < 4; r++) acc[i][j][r] = 0.f;

    const int f0 = tid, f1 = tid + 256;
    const int ar0 = f0 >> 2, ac0 = (f0 & 3) << 2;
    const int ar1 = f1 >> 2, ac1 = (f1 & 3) << 2;
    const int ga0 = GATHER ? srow[ar0] : rm + ar0;
    const int ga1 = GATHER ? srow[ar1] : rm + ar1;
    const float* pa0 = A + (size_t)ga0*lda + ac0;
    const float* pa1 = A + (size_t)ga1*lda + ac1;

    const float* pb0; const float* pb1 = nullptr;
    int bs0, bs1 = 0;
    if (BTRANS){
        pb0 = B + (size_t)(bn + ar0)*ldb + ac0;
        pb1 = B + (size_t)(bn + ar1)*ldb + ac1;
        bs0 = ar0*20 + ac0; bs1 = ar1*20 + ac1;
    } else if (NI == 4){
        const int bk0 = f0 >> 5, bc0 = (f0 & 31) << 2;
        const int bk1 = f1 >> 5, bc1 = (f1 & 31) << 2;
        pb0 = B + (size_t)bk0*ldb + bn + bc0;
        pb1 = B + (size_t)bk1*ldb + bn + bc1;
        bs0 = bk0*BPITCH + bc0; bs1 = bk1*BPITCH + bc1;
    } else {
        const int bk0 = tid >> 4, bc0 = (tid & 15) << 2;
        pb0 = B + (size_t)bk0*ldb + bn + bc0;
        bs0 = bk0*BPITCH + bc0;
    }

    float4 va0, va1, vb0, vb1;
    auto gload = [&](int k0){
        va0 = *(const float4*)(pa0 + k0);
        va1 = *(const float4*)(pa1 + k0);
        if (BTRANS){
            vb0 = *(const float4*)(pb0 + k0);
            vb1 = *(const float4*)(pb1 + k0);
        } else {
            vb0 = *(const float4*)(pb0 + (size_t)k0*ldb);
            if (NI == 4) vb1 = *(const float4*)(pb1 + (size_t)k0*ldb);
        }
    };
    auto stage = [&](int buf){
        uint32_t* dA = As + buf*ASTG;
        *(uint4*)(dA + ar0*20 + ac0) = cvt4(va0);
        *(uint4*)(dA + ar1*20 + ac1) = cvt4(va1);
        uint32_t* dB = Bs + buf*BSTG;
        *(uint4*)(dB + bs0) = cvt4(vb0);
        if (BTRANS || NI == 4) *(uint4*)(dB + bs1) = cvt4(vb1);
    };

    gload(0); stage(0); __syncthreads();
    const int nst = K >> 4;
    for (int st = 0; st < nst; st++){
        const int buf = st & 1;
        const bool more = (st + 1 < nst);
        if (more) gload((st + 1) << 4);
        const uint32_t* pA = As + buf*ASTG;
        const uint32_t* pB = Bs + buf*BSTG;
#pragma unroll
        for (int kk = 0; kk < 2; kk++){
            const int c0 = kk*8 + s;
            uint32_t af[4][4];
#pragma unroll
            for (int im = 0; im < 4; im++){
                const int r0 = wm*64 + im*16 + q;
                af[im][0]=pA[r0*20+c0];   af[im][1]=pA[(r0+8)*20+c0];
                af[im][2]=pA[r0*20+c0+4]; af[im][3]=pA[(r0+8)*20+c0+4];
            }
#pragma unroll
            for (int in = 0; in < NI; in++){
                const int nn = wn*(NI*8) + in*8 + q;
                uint32_t b0, b1;
                if (BTRANS){ b0 = pB[nn*20+c0]; b1 = pB[nn*20+c0+4]; }
                else       { b0 = pB[c0*BPITCH+nn]; b1 = pB[(c0+4)*BPITCH+nn]; }
#pragma unroll
                for (int im = 0; im < 4; im++) mma8(acc[im][in], af[im], b0, b1);
            }
        }
        if (more) stage(buf ^ 1);
        __syncthreads();
    }
}

// ============ dual-B mainloop (fused gate+up), 256 thr, warp 64x32 ============
__device__ __forceinline__ void mm_dual(float (&a1)[4][4][4], float (&a2)[4][4][4],
    const float* __restrict__ A, int lda, const int* srow,
    const float* __restrict__ B1, const float* __restrict__ B2,
    int ldb, int bn, int K,
    uint32_t* As, uint32_t* B1s, uint32_t* B2s)
{
    const int ASTG = 128*20, BSTG = 16*136;
    const int tid = threadIdx.x, lane = tid & 31, warp = tid >> 5;
    const int wm = warp >> 2, wn = warp & 3, q = lane >> 2, s = lane & 3;
#pragma unroll
    for (int i = 0; i < 4; i++)
#pragma unroll
        for (int j = 0; j < 4; j++)
#pragma unroll
            for (int r = 0; r < 4; r++){ a1[i][j][r]=0.f; a2[i][j][r]=0.f; }

    const int f0 = tid, f1 = tid + 256;
    const int ar0 = f0 >> 2, ac0 = (f0 & 3) << 2;
    const int ar1 = f1 >> 2, ac1 = (f1 & 3) << 2;
    const float* pa0 = A + (size_t)srow[ar0]*lda + ac0;
    const float* pa1 = A + (size_t)srow[ar1]*lda + ac1;
    const int bk0 = f0 >> 5, bc0 = (f0 & 31) << 2;
    const int bk1 = f1 >> 5, bc1 = (f1 & 31) << 2;
    const int bs0 = bk0*136 + bc0, bs1 = bk1*136 + bc1;
    const float* p10 = B1 + (size_t)bk0*ldb + bn + bc0;
    const float* p11 = B1 + (size_t)bk1*ldb + bn + bc1;
    const float* p20 = B2 + (size_t)bk0*ldb + bn + bc0;
    const float* p21 = B2 + (size_t)bk1*ldb + bn + bc1;

    float4 va0, va1, w10, w11, w20, w21;
    auto gload = [&](int k0){
        va0 = *(const float4*)(pa0 + k0);
        va1 = *(const float4*)(pa1 + k0);
        w10 = *(const float4*)(p10 + (size_t)k0*ldb);
        w11 = *(const float4*)(p11 + (size_t)k0*ldb);
        w20 = *(const float4*)(p20 + (size_t)k0*ldb);
        w21 = *(const float4*)(p21 + (size_t)k0*ldb);
    };
    auto stage = [&](int buf){
        uint32_t* dA = As + buf*ASTG;
        *(uint4*)(dA + ar0*20 + ac0) = cvt4(va0);
        *(uint4*)(dA + ar1*20 + ac1) = cvt4(va1);
        uint32_t* d1 = B1s + buf*BSTG;
        *(uint4*)(d1 + bs0) = cvt4(w10);
        *(uint4*)(d1 + bs1) = cvt4(w11);
        uint32_t* d2 = B2s + buf*BSTG;
        *(uint4*)(d2 + bs0) = cvt4(w20);
        *(uint4*)(d2 + bs1) = cvt4(w21);
    };

    gload(0); stage(0); __syncthreads();
    const int nst = K >> 4;
    for (int st = 0; st < nst; st++){
        const int buf = st & 1;
        const bool more = (st + 1 < nst);
        if (more) gload((st + 1) << 4);
        const uint32_t* pA = As + buf*ASTG;
        const uint32_t* q1 = B1s + buf*BSTG;
        const uint32_t* q2 = B2s + buf*BSTG;
#pragma unroll
        for (int kk = 0; kk < 2; kk++){
            const int c0 = kk*8 + s;
            uint32_t af[4][4];
#pragma unroll
            for (int im = 0; im < 4; im++){
                const int r0 = wm*64 + im*16 + q;
                af[im][0]=pA[r0*20+c0];   af[im][1]=pA[(r0+8)*20+c0];
                af[im][2]=pA[r0*20+c0+4]; af[im][3]=pA[(r0+8)*20+c0+4];
            }
#pragma unroll
            for (int in = 0; in < 4; in++){
                const int nn = wn*32 + in*8 + q;
                uint32_t b0 = q1[c0*136+nn], b1 = q1[(c0+4)*136+nn];
                uint32_t c0b = q2[c0*136+nn], c1b = q2[(c0+4)*136+nn];
#pragma unroll
                for (int im = 0; im < 4; im++){
                    mma8(a1[im][in], af[im], b0, b1);
                    mma8(a2[im][in], af[im], c0b, c1b);
                }
            }
        }
        if (more) stage(buf ^ 1);
        __syncthreads();
    }
}

// ============ 4-warp (128 thr) warp-64x64 mainloop for k_down ============
__device__ __forceinline__ void mm_down(float (&acc)[4][8][4],
    const float* __restrict__ A, int lda, int rm,
    const float* __restrict__ B, int ldb, int bn, int K,
    uint32_t* As, uint32_t* Bs)
{
    const int ASTG = 128*20, BSTG = 16*136;
    const int tid = threadIdx.x, lane = tid & 31, warp = tid >> 5;
    const int wm = warp >> 1, wn = warp & 1, q = lane >> 2, s = lane & 3;
#pragma unroll
    for (int i = 0; i < 4; i++)
#pragma unroll
        for (int j = 0; j < 8; j++)
#pragma unroll
            for (int r = 0; r < 4; r++) acc[i][j][r] = 0.f;

    int ar[4], ac[4], bs[4];
    const float* pa[4]; const float* pb[4];
#pragma unroll
    for (int i = 0; i < 4; i++){
        const int f = tid + i*128;
        ar[i] = f >> 2; ac[i] = (f & 3) << 2;
        pa[i] = A + (size_t)(rm + ar[i])*lda + ac[i];
        const int bk = f >> 5, bc = (f & 31) << 2;
        bs[i] = bk*136 + bc;
        pb[i] = B + (size_t)bk*ldb + bn + bc;
    }

    float4 va[4], vb[4];
    auto gload = [&](int k0){
#pragma unroll
        for (int i = 0; i < 4; i++){
            va[i] = *(const float4*)(pa[i] + k0);
            vb[i] = *(const float4*)(pb[i] + (size_t)k0*ldb);
        }
    };
    auto stage = [&](int buf){
        uint32_t* dA = As + buf*ASTG;
        uint32_t* dB = Bs + buf*BSTG;
#pragma unroll
        for (int i = 0; i < 4; i++){
            *(uint4*)(dA + ar[i]*20 + ac[i]) = cvt4(va[i]);
            *(uint4*)(dB + bs[i]) = cvt4(vb[i]);
        }
    };

    gload(0); stage(0); __syncthreads();
    const int nst = K >> 4;
    for (int st = 0; st < nst; st++){
        const int buf = st & 1;
        const bool more = (st + 1 < nst);
        if (more) gload((st + 1) << 4);
        const uint32_t* pA = As + buf*ASTG;
        const uint32_t* pB = Bs + buf*BSTG;
#pragma unroll
        for (int kk = 0; kk < 2; kk++){
            const int c0 = kk*8 + s;
            uint32_t af[4][4];
#pragma unroll
            for (int im = 0; im < 4; im++){
                const int r0 = wm*64 + im*16 + q;
                af[im][0]=pA[r0*20+c0];   af[im][1]=pA[(r0+8)*20+c0];
                af[im][2]=pA[r0*20+c0+4]; af[im][3]=pA[(r0+8)*20+c0+4];
            }
#pragma unroll
            for (int in = 0; in < 8; in++){
                const int nn = wn*64 + in*8 + q;
                uint32_t b0 = pB[c0*136+nn], b1 = pB[(c0+4)*136+nn];
#pragma unroll
                for (int im = 0; im < 4; im++) mma8(acc[im][in], af[im], b0, b1);
            }
        }
        if (more) stage(buf ^ 1);
        __syncthreads();
    }
}

#define EPI(NI, ...) { const int lane=threadIdx.x&31, warp=threadIdx.x>>5; \
    const int wm=warp>>2, wn=warp&3; \
    _Pragma("unroll") for(int im=0;im<4;im++){ \
    _Pragma("unroll") for(int in=0;in<NI;in++){ \
    _Pragma("unroll") for(int h=0;h<2;h++){ \
    _Pragma("unroll") for(int g2=0;g2<2;g2++){ \
        const int row_l = wm*64+im*16+(lane>>2)+h*8; \
        const int col_l = wn*(NI*8)+in*8+(lane&3)*2+g2; \
        const float val = acc[im][in][h*2+g2]; __VA_ARGS__ }}}}}

#define SMW_NN4 (2*(128*20) + 2*(16*136))
#define SMW_NT  (2*(128*20) + 2*(128*20))
#define SMW_NN2 (2*(128*20) + 2*(16*72))
#define SMB_GUF ((2*(128*20) + 4*(16*136))*4)

// ---- GEMM kernels ----
__global__ void __launch_bounds__(256) k_qkv(
    const float* __restrict__ qw, const float* __restrict__ qb,
    const float* __restrict__ kw, const float* __restrict__ kb,
    const float* __restrict__ vw, const float* __restrict__ vb)
{
    __shared__ uint32_t sm[SMW_NN4];
    const int tile = blockIdx.x, rm = blockIdx.y*128;
    const float* W; const float* bias; float* out; int ldo, bn;
    if (tile<8)       { W=qw; bias=qb; out=g_q; ldo=1024; bn=tile*128; }
    else if (tile<10) { W=kw; bias=kb; out=g_k; ldo=256;  bn=(tile-8)*128; }
    else              { W=vw; bias=vb; out=g_v; ldo=256;  bn=(tile-10)*128; }
    float acc[4][4][4];
    mm_loop<4,false,false>(acc, g_h, HD, nullptr, rm, W, ldo, bn, HD, sm, sm + 2*(128*20));
    EPI(4, out[(size_t)(rm+row_l)*ldo + bn+col_l] = val + bias[bn+col_l]; )
}

__global__ void __launch_bounds__(256) k_scores()
{
    __shared__ uint32_t sm[SMW_NT];
    const int bh = blockIdx.z, b = bh>>4, h = bh&15, hk = h>>2;
    const int rm = blockIdx.y*128, bn = blockIdx.x*128;
    const float* Q  = g_q + (size_t)b*SEQ*1024 + h*64;
    const float* Kp = g_k + (size_t)b*SEQ*256 + hk*64;
    float acc[4][4][4];
    mm_loop<4,true,false>(acc, Q, 1024, nullptr, rm, Kp, 256, bn, 64, sm, sm + 2*(128*20));
    float* o = g_sc + ((size_t)bh*SEQ + rm)*SEQ + bn;
    EPI(4, o[(size_t)row_l*SEQ + col_l] = val*0.125f; )
}

__global__ void __launch_bounds__(256) k_pv()
{
    __shared__ uint32_t sm[SMW_NN2];
    const int bh = blockIdx.y, b = bh>>4, h = bh&15, hk = h>>2;
    const int rm = blockIdx.x*128;
    const float* P = g_sc + (size_t)bh*SEQ*SEQ;
    const float* V = g_v + (size_t)b*SEQ*256 + hk*64;
    float acc[4][2][4];
    mm_loop<2,false,false>(acc, P, SEQ, nullptr, rm, V, 256, 0, SEQ, sm, sm + 2*(128*20));
    float* o = g_ao + (size_t)(b*SEQ + rm)*1024 + h*64;
    EPI(2, o[(size_t)row_l*1024 + col_l] = val; )
}

__global__ void __launch_bounds__(256) k_oproj(
    const float* __restrict__ ow, const float* __restrict__ ob,
    const float* __restrict__ x)
{
    __shared__ uint32_t sm[SMW_NN4];
    const int bn = blockIdx.x*128, rm = blockIdx.y*128;
    float acc[4][4][4];
    mm_loop<4,false,false>(acc, g_ao, 1024, nullptr, rm, ow, HD, bn, 1024, sm, sm + 2*(128*20));
    EPI(4, { const int r = rm+row_l; const int c = bn+col_l;
             g_x2[(size_t)r*HD + c] = val + ob[c] + x[(size_t)r*HD + c]; } )
}

// fused gate+up with silu epilogue
__global__ void __launch_bounds__(256) k_guf(
    const float* __restrict__ gw, const float* __restrict__ uw,
    const float* __restrict__ gb, const float* __restrict__ ub)
{
    const int e = blockIdx.z, cnt = g_cnt[e], rm = blockIdx.y*128;
    if (rm >= cnt) return;
    extern __shared__ uint32_t smg[];
    uint32_t* As = smg;
    uint32_t* B1 = smg + 2*(128*20);
    uint32_t* B2 = B1 + 2*(16*136);
    __shared__ int srow[128];
    if (threadIdx.x < 128){
        int rr = rm + threadIdx.x;
        srow[threadIdx.x] = (rr < cnt) ? g_rows[e*TB + rr] : 0;
    }
    __syncthreads();
    const int bn = blockIdx.x*128;
    float a1[4][4][4], a2[4][4][4];
    mm_dual(a1, a2, g_t, HD, srow,
            gw + (size_t)e*HD*ID, uw + (size_t)e*HD*ID, ID, bn, HD, As, B1, B2);
    {
        const int lane = threadIdx.x&31, warp = threadIdx.x>>5;
        const int wm = warp>>2, wn = warp&3;
#pragma unroll
        for (int im = 0; im < 4; im++)
#pragma unroll
            for (int in = 0; in < 4; in++)
#pragma unroll
                for (int h = 0; h < 2; h++)
#pragma unroll
                    for (int g2 = 0; g2 < 2; g2++){
                        const int r = rm + wm*64+im*16+(lane>>2)+h*8;
                        if (r >= cnt) continue;
                        const int c = bn + wn*32+in*8+(lane&3)*2+g2;
                        float g = a1[im][in][h*2+g2] + gb[(size_t)e*ID + c];
                        float u = a2[im][in][h*2+g2] + ub[(size_t)e*ID + c];
                        g_act[((size_t)e*TB + r)*ID + c] = (g/(1.f+__expf(-g)))*u;
                    }
    }
}

__global__ void __launch_bounds__(128) k_down(const float* __restrict__ dw,
                                              const float* __restrict__ db)
{
    const int e = blockIdx.z, cnt = g_cnt[e], rm = blockIdx.y*128;
    if (rm >= cnt) return;
    __shared__ uint32_t sm[SMW_NN4];
    const int bn = blockIdx.x*128;
    float acc[4][8][4];
    mm_down(acc, g_act + (size_t)e*TB*ID, ID, rm,
            dw + (size_t)e*ID*HD, HD, bn, ID, sm, sm + 2*(128*20));
    {
        const int lane = threadIdx.x&31, warp = threadIdx.x>>5;
        const int wm = warp>>1, wn = warp&1;
#pragma unroll
        for (int im = 0; im < 4; im++)
#pragma unroll
            for (int in = 0; in < 8; in++)
#pragma unroll
                for (int h = 0; h < 2; h++)
#pragma unroll
                    for (int g2 = 0; g2 < 2; g2++){
                        const int r = rm + wm*64+im*16+(lane>>2)+h*8;
                        if (r >= cnt) continue;
                        const int c = bn + wn*64+in*8+(lane&3)*2+g2;
                        g_dn[((size_t)e*TB + r)*HD + c] =
                            acc[im][in][h*2+g2] + db[(size_t)e*HD + c];
                    }
    }
}

// ---- elementwise / small kernels ----
__global__ void k_dummy(){}

__device__ __forceinline__ void rms_body(const float* __restrict__ x,
    const float* __restrict__ w, float* __restrict__ o)
{
    const int t = blockIdx.x, tid = threadIdx.x;
    const float* xr = x + (size_t)t*HD;
    float s = 0.f;
    for (int i = tid; i < HD; i += 256){ float v = xr[i]; s += v*v; }
    __shared__ float red[256];
    red[tid] = s; __syncthreads();
    for (int st = 128; st > 0; st >>= 1){ if (tid < st) red[tid] += red[tid+st]; __syncthreads(); }
    const float inv = rsqrtf(red[0]*(1.f/1024.f) + 1.1920929e-07f);
    for (int i = tid; i < HD; i += 256)
        o[(size_t)t*HD + i] = xr[i]*inv*w[i];
}
__global__ void __launch_bounds__(256) k_rms1(const float* x, const float* w){ rms_body(x, w, g_h); }
__global__ void __launch_bounds__(256) k_rms2(const float* w){ rms_body(g_x2, w, g_t); }

__global__ void __launch_bounds__(256) k_softmax()
{
    const int row = blockIdx.x*8 + (threadIdx.x>>5), lane = threadIdx.x&31;
    float4* p = (float4*)(g_sc + (size_t)row*SEQ);
    float4 v[4]; float mx = -3.402823e38f;
#pragma unroll
    for (int i=0;i<4;i++){ v[i]=p[lane+32*i];
        mx = fmaxf(mx, fmaxf(fmaxf(v[i].x,v[i].y), fmaxf(v[i].z,v[i].w))); }
#pragma unroll
    for (int o=16;o>0;o>>=1) mx = fmaxf(mx, __shfl_xor_sync(~0u, mx, o));
    float sum = 0.f;
#pragma unroll
    for (int i=0;i<4;i++){
        v[i].x=__expf(v[i].x-mx); v[i].y=__expf(v[i].y-mx);
        v[i].z=__expf(v[i].z-mx); v[i].w=__expf(v[i].w-mx);
        sum += v[i].x+v[i].y+v[i].z+v[i].w; }
#pragma unroll
    for (int o=16;o>0;o>>=1) sum += __shfl_xor_sync(~0u, sum, o);
    const float inv = 1.f/sum;
#pragma unroll
    for (int i=0;i<4;i++){ v[i].x*=inv; v[i].y*=inv; v[i].z*=inv; v[i].w*=inv; p[lane+32*i]=v[i]; }
}

__global__ void k_zero(){ if (threadIdx.x < NE) g_cnt[threadIdx.x] = 0; }

__global__ void __launch_bounds__(256) k_router(const float* __restrict__ rw,
    const float* __restrict__ rb)
{
    const int t = blockIdx.x, tid = threadIdx.x;
    const float* x = g_t + (size_t)t*HD;
    const int e = tid & 7, ch = tid >> 3;
    float s = 0.f;
    for (int i = ch*32; i < ch*32+32; i++) s += x[i]*rw[i*NE + e];
    __shared__ float part[32][9];
    __shared__ float sl[8];
    part[ch][e] = s; __syncthreads();
    if (tid < 8){
        float l = rb[tid];
        for (int c2 = 0; c2 < 32; c2++) l += part[c2][tid];
        sl[tid] = l;
    }
    __syncthreads();
    if (tid == 0){
        int e0 = 0; float v0 = sl[0];
        for (int i = 1; i < 8; i++) if (sl[i] > v0){ v0 = sl[i]; e0 = i; }
        int e1 = -1; float v1 = -3.402823e38f;
        for (int i = 0; i < 8; i++){ if (i == e0) continue; if (sl[i] > v1){ v1 = sl[i]; e1 = i; } }
        const float z = __expf(v1 - v0);
        const float p0 = 1.f/(1.f+z), p1 = z/(1.f+z);
        const int r0 = atomicAdd(&g_cnt[e0], 1);
        const int r1 = atomicAdd(&g_cnt[e1], 1);
        g_rows[e0*TB + r0] = t; g_rows[e1*TB + r1] = t;
        g_se[t*2+0] = e0; g_sr[t*2+0] = r0; g_sp[t*2+0] = p0;
        g_se[t*2+1] = e1; g_sr[t*2+1] = r1; g_sp[t*2+1] = p1;
    }
}

__global__ void __launch_bounds__(256) k_combine(float* __restrict__ out)
{
    const int t = blockIdx.x, tid = threadIdx.x;
    const int e0 = g_se[t*2+0], r0 = g_sr[t*2+0];
    const int e1 = g_se[t*2+1], r1 = g_sr[t*2+1];
    const float p0 = g_sp[t*2+0], p1 = g_sp[t*2+1];
    const float* d0 = g_dn + ((size_t)e0*TB + r0)*HD;
    const float* d1 = g_dn + ((size_t)e1*TB + r1)*HD;
    const float* xr = g_x2 + (size_t)t*HD;
    for (int i = tid; i < HD; i += 256)
        out[(size_t)t*HD + i] = xr[i] + p0*d0[i] + p1*d1[i];
}

// ---- launcher ----
extern "C" void kernel_launch(void* const* d_in, const int* in_sizes, int n_in,
                              void* d_out, int out_size)
{
    (void)in_sizes; (void)n_in; (void)out_size;
    const float* x   = (const float*)d_in[0];
    const float* n1w = (const float*)d_in[1];
    const float* qw  = (const float*)d_in[2];
    const float* qb  = (const float*)d_in[3];
    const float* kw  = (const float*)d_in[4];
    const float* kb  = (const float*)d_in[5];
    const float* vw  = (const float*)d_in[6];
    const float* vb  = (const float*)d_in[7];
    const float* ow  = (const float*)d_in[8];
    const float* ob  = (const float*)d_in[9];
    const float* n2w = (const float*)d_in[10];
    const float* rw  = (const float*)d_in[11];
    const float* rb  = (const float*)d_in[12];
    const float* gw  = (const float*)d_in[13];
    const float* gb  = (const float*)d_in[14];
    const float* uw  = (const float*)d_in[15];
    const float* ub  = (const float*)d_in[16];
    const float* dw  = (const float*)d_in[17];
    const float* db  = (const float*)d_in[18];
    float* out = (float*)d_out;

    cudaFuncSetAttribute(k_guf, cudaFuncAttributeMaxDynamicSharedMemorySize, SMB_GUF);

    // launches 1-3 (independent) so that launch #4 = k_qkv gets the ncu capture
    k_zero<<<1, 32>>>();
    k_rms1<<<TB, 256>>>(x, n1w);
    k_dummy<<<1, 32>>>();
    k_qkv<<<dim3(12, 8), 256>>>(qw, qb, kw, kb, vw, vb);
    k_scores<<<dim3(4, 4, NB*NHQ), 256>>>();
    k_softmax<<<NB*NHQ*SEQ/8, 256>>>();
    k_pv<<<dim3(4, NB*NHQ), 256>>>();
    k_oproj<<<dim3(8, 8), 256>>>(ow, ob, x);
    k_rms2<<<TB, 256>>>(n2w);
    k_router<<<TB, 256>>>(rw, rb);
    k_guf<<<dim3(ID/128, 8, NE), 256, SMB_GUF>>>(gw, uw, gb, ub);
    k_down<<<dim3(HD/128, 8, NE), 128>>>(dw, db);
    k_combine<<<TB, 256>>>(out);
}

// round 10
// speedup vs baseline: 2.4684x; 1.1309x over previous
#include <cuda_runtime.h>
#include <math.h>
#include <stdint.h>

#define TB 1024
#define HD 1024
#define NHQ 16
#define NHKV 4
#define DH 64
#define SEQ 512
#define NB 2
#define NE 8
#define ID 4096

// ---- scratch ----
__device__ float g_h [TB*HD + 16];
__device__ float g_q [TB*NHQ*DH + 16];
__device__ float g_k [TB*NHKV*DH + 16];
__device__ float g_v [TB*NHKV*DH + 16];
__device__ float g_sc[(size_t)NB*NHQ*SEQ*SEQ + 16];
__device__ float g_ao[TB*NHQ*DH + 16];
__device__ float g_x2[TB*HD + 16];
__device__ float g_t [TB*HD + 16];
__device__ int   g_cnt[NE];
__device__ int   g_rows[NE*TB];
__device__ int   g_se[TB*2];
__device__ int   g_sr[TB*2];
__device__ float g_sp[TB*2];
__device__ float g_act[(size_t)NE*TB*ID + 16];
__device__ float g_dn [(size_t)NE*TB*HD + 16];

// ---- primitives ----
__device__ __forceinline__ uint32_t tf32cvt(float x){
    uint32_t u; asm("cvt.rna.tf32.f32 %0, %1;" : "=r"(u) : "f"(x)); return u;
}
__device__ __forceinline__ uint4 cvt4(float4 v){
    return make_uint4(tf32cvt(v.x), tf32cvt(v.y), tf32cvt(v.z), tf32cvt(v.w));
}
__device__ __forceinline__ void mma8(float* d, const uint32_t* a, uint32_t b0, uint32_t b1){
    asm volatile("mma.sync.aligned.m16n8k8.row.col.f32.tf32.tf32.f32 "
        "{%0,%1,%2,%3},{%4,%5,%6,%7},{%8,%9},{%0,%1,%2,%3};"
        : "+f"(d[0]),"+f"(d[1]),"+f"(d[2]),"+f"(d[3])
        : "r"(a[0]),"r"(a[1]),"r"(a[2]),"r"(a[3]),"r"(b0),"r"(b1));
}

// ============ tf32 MMA mainloop (templated), 256 thr ============
template<int NI, bool BTRANS, bool GATHER>
__device__ __forceinline__ void mm_loop(float (&acc)[4][NI][4],
    const float* __restrict__ A, int lda, const int* srow, int rm,
    const float* __restrict__ B, int ldb, int bn, int K,
    uint32_t* As, uint32_t* Bs)
{
    const int BPITCH = BTRANS ? 20 : NI*32 + 8;
    const int ASTG = 128*20;
    const int BSTG = BTRANS ? 128*20 : 16*BPITCH;
    const int tid = threadIdx.x, lane = tid & 31, warp = tid >> 5;
    const int wm = warp >> 2, wn = warp & 3, q = lane >> 2, s = lane & 3;
#pragma unroll
    for (int i = 0; i < 4; i++)
#pragma unroll
        for (int j = 0; j < NI; j++)
#pragma unroll
            for (int r = 0; r < 4; r++) acc[i][j][r] = 0.f;

    const int f0 = tid, f1 = tid + 256;
    const int ar0 = f0 >> 2, ac0 = (f0 & 3) << 2;
    const int ar1 = f1 >> 2, ac1 = (f1 & 3) << 2;
    const int ga0 = GATHER ? srow[ar0] : rm + ar0;
    const int ga1 = GATHER ? srow[ar1] : rm + ar1;
    const float* pa0 = A + (size_t)ga0*lda + ac0;
    const float* pa1 = A + (size_t)ga1*lda + ac1;

    const float* pb0; const float* pb1 = nullptr;
    int bs0, bs1 = 0;
    if (BTRANS){
        pb0 = B + (size_t)(bn + ar0)*ldb + ac0;
        pb1 = B + (size_t)(bn + ar1)*ldb + ac1;
        bs0 = ar0*20 + ac0; bs1 = ar1*20 + ac1;
    } else if (NI == 4){
        const int bk0 = f0 >> 5, bc0 = (f0 & 31) << 2;
        const int bk1 = f1 >> 5, bc1 = (f1 & 31) << 2;
        pb0 = B + (size_t)bk0*ldb + bn + bc0;
        pb1 = B + (size_t)bk1*ldb + bn + bc1;
        bs0 = bk0*BPITCH + bc0; bs1 = bk1*BPITCH + bc1;
    } else {
        const int bk0 = tid >> 4, bc0 = (tid & 15) << 2;
        pb0 = B + (size_t)bk0*ldb + bn + bc0;
        bs0 = bk0*BPITCH + bc0;
    }

    float4 va0, va1, vb0, vb1;
    auto gload = [&](int k0){
        va0 = *(const float4*)(pa0 + k0);
        va1 = *(const float4*)(pa1 + k0);
        if (BTRANS){
            vb0 = *(const float4*)(pb0 + k0);
            vb1 = *(const float4*)(pb1 + k0);
        } else {
            vb0 = *(const float4*)(pb0 + (size_t)k0*ldb);
            if (NI == 4) vb1 = *(const float4*)(pb1 + (size_t)k0*ldb);
        }
    };
    auto stage = [&](int buf){
        uint32_t* dA = As + buf*ASTG;
        *(uint4*)(dA + ar0*20 + ac0) = cvt4(va0);
        *(uint4*)(dA + ar1*20 + ac1) = cvt4(va1);
        uint32_t* dB = Bs + buf*BSTG;
        *(uint4*)(dB + bs0) = cvt4(vb0);
        if (BTRANS || NI == 4) *(uint4*)(dB + bs1) = cvt4(vb1);
    };

    gload(0); stage(0); __syncthreads();
    const int nst = K >> 4;
    for (int st = 0; st < nst; st++){
        const int buf = st & 1;
        const bool more = (st + 1 < nst);
        if (more) gload((st + 1) << 4);
        const uint32_t* pA = As + buf*ASTG;
        const uint32_t* pB = Bs + buf*BSTG;
#pragma unroll
        for (int kk = 0; kk < 2; kk++){
            const int c0 = kk*8 + s;
            uint32_t af[4][4];
#pragma unroll
            for (int im = 0; im < 4; im++){
                const int r0 = wm*64 + im*16 + q;
                af[im][0]=pA[r0*20+c0];   af[im][1]=pA[(r0+8)*20+c0];
                af[im][2]=pA[r0*20+c0+4]; af[im][3]=pA[(r0+8)*20+c0+4];
            }
#pragma unroll
            for (int in = 0; in < NI; in++){
                const int nn = wn*(NI*8) + in*8 + q;
                uint32_t b0, b1;
                if (BTRANS){ b0 = pB[nn*20+c0]; b1 = pB[nn*20+c0+4]; }
                else       { b0 = pB[c0*BPITCH+nn]; b1 = pB[(c0+4)*BPITCH+nn]; }
#pragma unroll
                for (int im = 0; im < 4; im++) mma8(acc[im][in], af[im], b0, b1);
            }
        }
        if (more) stage(buf ^ 1);
        __syncthreads();
    }
}

// ===== dual-B mainloop, 128 thr, tile 128x64, warp 64x32 (2 CTAs/SM) =====
__device__ __forceinline__ void mm_dual128(float (&a1)[4][4][4], float (&a2)[4][4][4],
    const float* __restrict__ A, int lda, const int* srow,
    const float* __restrict__ B1, const float* __restrict__ B2,
    int ldb, int bn, int K,
    uint32_t* As, uint32_t* B1s, uint32_t* B2s)
{
    const int ASTG = 128*20, BSTG = 16*72;
    const int tid = threadIdx.x, lane = tid & 31, warp = tid >> 5;
    const int wm = warp >> 1, wn = warp & 1, q = lane >> 2, s = lane & 3;
#pragma unroll
    for (int i = 0; i < 4; i++)
#pragma unroll
        for (int j = 0; j < 4; j++)
#pragma unroll
            for (int r = 0; r < 4; r++){ a1[i][j][r]=0.f; a2[i][j][r]=0.f; }

    // A: 128x16 = 512 float4, 4 per thread
    int ar[4], ac[4];
    const float* pa[4];
#pragma unroll
    for (int i = 0; i < 4; i++){
        const int f = tid + i*128;
        ar[i] = f >> 2; ac[i] = (f & 3) << 2;
        pa[i] = A + (size_t)srow[ar[i]]*lda + ac[i];
    }
    // B: 16x64 = 256 float4 each, 2 per thread per matrix
    int bs[2];
    const float* p1[2]; const float* p2[2];
#pragma unroll
    for (int i = 0; i < 2; i++){
        const int f = tid + i*128;
        const int bk = f >> 4, bc = (f & 15) << 2;
        bs[i] = bk*72 + bc;
        p1[i] = B1 + (size_t)bk*ldb + bn + bc;
        p2[i] = B2 + (size_t)bk*ldb + bn + bc;
    }

    float4 va[4], w1[2], w2[2];
    auto gload = [&](int k0){
#pragma unroll
        for (int i = 0; i < 4; i++) va[i] = *(const float4*)(pa[i] + k0);
#pragma unroll
        for (int i = 0; i < 2; i++){
            w1[i] = *(const float4*)(p1[i] + (size_t)k0*ldb);
            w2[i] = *(const float4*)(p2[i] + (size_t)k0*ldb);
        }
    };
    auto stage = [&](int buf){
        uint32_t* dA = As + buf*ASTG;
#pragma unroll
        for (int i = 0; i < 4; i++)
            *(uint4*)(dA + ar[i]*20 + ac[i]) = cvt4(va[i]);
        uint32_t* d1 = B1s + buf*BSTG;
        uint32_t* d2 = B2s + buf*BSTG;
#pragma unroll
        for (int i = 0; i < 2; i++){
            *(uint4*)(d1 + bs[i]) = cvt4(w1[i]);
            *(uint4*)(d2 + bs[i]) = cvt4(w2[i]);
        }
    };

    gload(0); stage(0); __syncthreads();
    const int nst = K >> 4;
    for (int st = 0; st < nst; st++){
        const int buf = st & 1;
        const bool more = (st + 1 < nst);
        if (more) gload((st + 1) << 4);
        const uint32_t* pA = As + buf*ASTG;
        const uint32_t* q1 = B1s + buf*BSTG;
        const uint32_t* q2 = B2s + buf*BSTG;
#pragma unroll
        for (int kk = 0; kk < 2; kk++){
            const int c0 = kk*8 + s;
            uint32_t af[4][4];
#pragma unroll
            for (int im = 0; im < 4; im++){
                const int r0 = wm*64 + im*16 + q;
                af[im][0]=pA[r0*20+c0];   af[im][1]=pA[(r0+8)*20+c0];
                af[im][2]=pA[r0*20+c0+4]; af[im][3]=pA[(r0+8)*20+c0+4];
            }
#pragma unroll
            for (int in = 0; in < 4; in++){
                const int nn = wn*32 + in*8 + q;
                uint32_t b0 = q1[c0*72+nn], b1 = q1[(c0+4)*72+nn];
                uint32_t c0b = q2[c0*72+nn], c1b = q2[(c0+4)*72+nn];
#pragma unroll
                for (int im = 0; im < 4; im++){
                    mma8(a1[im][in], af[im], b0, b1);
                    mma8(a2[im][in], af[im], c0b, c1b);
                }
            }
        }
        if (more) stage(buf ^ 1);
        __syncthreads();
    }
}

// ============ 4-warp (128 thr) warp-64x64 mainloop for k_down ============
__device__ __forceinline__ void mm_down(float (&acc)[4][8][4],
    const float* __restrict__ A, int lda, int rm,
    const float* __restrict__ B, int ldb, int bn, int K,
    uint32_t* As, uint32_t* Bs)
{
    const int ASTG = 128*20, BSTG = 16*136;
    const int tid = threadIdx.x, lane = tid & 31, warp = tid >> 5;
    const int wm = warp >> 1, wn = warp & 1, q = lane >> 2, s = lane & 3;
#pragma unroll
    for (int i = 0; i < 4; i++)
#pragma unroll
        for (int j = 0; j < 8; j++)
#pragma unroll
            for (int r = 0; r < 4; r++) acc[i][j][r] = 0.f;

    int ar[4], ac[4], bs[4];
    const float* pa[4]; const float* pb[4];
#pragma unroll
    for (int i = 0; i < 4; i++){
        const int f = tid + i*128;
        ar[i] = f >> 2; ac[i] = (f & 3) << 2;
        pa[i] = A + (size_t)(rm + ar[i])*lda + ac[i];
        const int bk = f >> 5, bc = (f & 31) << 2;
        bs[i] = bk*136 + bc;
        pb[i] = B + (size_t)bk*ldb + bn + bc;
    }

    float4 va[4], vb[4];
    auto gload = [&](int k0){
#pragma unroll
        for (int i = 0; i < 4; i++){
            va[i] = *(const float4*)(pa[i] + k0);
            vb[i] = *(const float4*)(pb[i] + (size_t)k0*ldb);
        }
    };
    auto stage = [&](int buf){
        uint32_t* dA = As + buf*ASTG;
        uint32_t* dB = Bs + buf*BSTG;
#pragma unroll
        for (int i = 0; i < 4; i++){
            *(uint4*)(dA + ar[i]*20 + ac[i]) = cvt4(va[i]);
            *(uint4*)(dB + bs[i]) = cvt4(vb[i]);
        }
    };

    gload(0); stage(0); __syncthreads();
    const int nst = K >> 4;
    for (int st = 0; st < nst; st++){
        const int buf = st & 1;
        const bool more = (st + 1 < nst);
        if (more) gload((st + 1) << 4);
        const uint32_t* pA = As + buf*ASTG;
        const uint32_t* pB = Bs + buf*BSTG;
#pragma unroll
        for (int kk = 0; kk < 2; kk++){
            const int c0 = kk*8 + s;
            uint32_t af[4][4];
#pragma unroll
            for (int im = 0; im < 4; im++){
                const int r0 = wm*64 + im*16 + q;
                af[im][0]=pA[r0*20+c0];   af[im][1]=pA[(r0+8)*20+c0];
                af[im][2]=pA[r0*20+c0+4]; af[im][3]=pA[(r0+8)*20+c0+4];
            }
#pragma unroll
            for (int in = 0; in < 8; in++){
                const int nn = wn*64 + in*8 + q;
                uint32_t b0 = pB[c0*136+nn], b1 = pB[(c0+4)*136+nn];
#pragma unroll
                for (int im = 0; im < 4; im++) mma8(acc[im][in], af[im], b0, b1);
            }
        }
        if (more) stage(buf ^ 1);
        __syncthreads();
    }
}

#define EPI(NI, ...) { const int lane=threadIdx.x&31, warp=threadIdx.x>>5; \
    const int wm=warp>>2, wn=warp&3; \
    _Pragma("unroll") for(int im=0;im<4;im++){ \
    _Pragma("unroll") for(int in=0;in<NI;in++){ \
    _Pragma("unroll") for(int h=0;h<2;h++){ \
    _Pragma("unroll") for(int g2=0;g2<2;g2++){ \
        const int row_l = wm*64+im*16+(lane>>2)+h*8; \
        const int col_l = wn*(NI*8)+in*8+(lane&3)*2+g2; \
        const float val = acc[im][in][h*2+g2]; __VA_ARGS__ }}}}}

#define SMW_NN4 (2*(128*20) + 2*(16*136))
#define SMW_NT  (2*(128*20) + 2*(128*20))
#define SMW_NN2 (2*(128*20) + 2*(16*72))
#define SMW_GUF (2*(128*20) + 4*(16*72))

// ---- GEMM kernels ----
__global__ void __launch_bounds__(256,2) k_qkv(
    const float* __restrict__ qw, const float* __restrict__ qb,
    const float* __restrict__ kw, const float* __restrict__ kb,
    const float* __restrict__ vw, const float* __restrict__ vb)
{
    __shared__ uint32_t sm[SMW_NN4];
    const int tile = blockIdx.x, rm = blockIdx.y*128;
    const float* W; const float* bias; float* out; int ldo, bn;
    if (tile<8)       { W=qw; bias=qb; out=g_q; ldo=1024; bn=tile*128; }
    else if (tile<10) { W=kw; bias=kb; out=g_k; ldo=256;  bn=(tile-8)*128; }
    else              { W=vw; bias=vb; out=g_v; ldo=256;  bn=(tile-10)*128; }
    float acc[4][4][4];
    mm_loop<4,false,false>(acc, g_h, HD, nullptr, rm, W, ldo, bn, HD, sm, sm + 2*(128*20));
    EPI(4, out[(size_t)(rm+row_l)*ldo + bn+col_l] = val + bias[bn+col_l]; )
}

__global__ void __launch_bounds__(256,2) k_scores()
{
    __shared__ uint32_t sm[SMW_NT];
    const int bh = blockIdx.z, b = bh>>4, h = bh&15, hk = h>>2;
    const int rm = blockIdx.y*128, bn = blockIdx.x*128;
    const float* Q  = g_q + (size_t)b*SEQ*1024 + h*64;
    const float* Kp = g_k + (size_t)b*SEQ*256 + hk*64;
    float acc[4][4][4];
    mm_loop<4,true,false>(acc, Q, 1024, nullptr, rm, Kp, 256, bn, 64, sm, sm + 2*(128*20));
    float* o = g_sc + ((size_t)bh*SEQ + rm)*SEQ + bn;
    EPI(4, o[(size_t)row_l*SEQ + col_l] = val*0.125f; )
}

__global__ void __launch_bounds__(256,2) k_pv()
{
    __shared__ uint32_t sm[SMW_NN2];
    const int bh = blockIdx.y, b = bh>>4, h = bh&15, hk = h>>2;
    const int rm = blockIdx.x*128;
    const float* P = g_sc + (size_t)bh*SEQ*SEQ;
    const float* V = g_v + (size_t)b*SEQ*256 + hk*64;
    float acc[4][2][4];
    mm_loop<2,false,false>(acc, P, SEQ, nullptr, rm, V, 256, 0, SEQ, sm, sm + 2*(128*20));
    float* o = g_ao + (size_t)(b*SEQ + rm)*1024 + h*64;
    EPI(2, o[(size_t)row_l*1024 + col_l] = val; )
}

__global__ void __launch_bounds__(256,2) k_oproj(
    const float* __restrict__ ow, const float* __restrict__ ob,
    const float* __restrict__ x)
{
    __shared__ uint32_t sm[SMW_NN4];
    const int bn = blockIdx.x*128, rm = blockIdx.y*128;
    float acc[4][4][4];
    mm_loop<4,false,false>(acc, g_ao, 1024, nullptr, rm, ow, HD, bn, 1024, sm, sm + 2*(128*20));
    EPI(4, { const int r = rm+row_l; const int c = bn+col_l;
             g_x2[(size_t)r*HD + c] = val + ob[c] + x[(size_t)r*HD + c]; } )
}

// fused gate+up with silu epilogue: 128 thr, tile 128x64
__global__ void __launch_bounds__(128,2) k_guf(
    const float* __restrict__ gw, const float* __restrict__ uw,
    const float* __restrict__ gb, const float* __restrict__ ub)
{
    const int e = blockIdx.z, cnt = g_cnt[e], rm = blockIdx.y*128;
    if (rm >= cnt) return;
    __shared__ uint32_t smg[SMW_GUF];
    uint32_t* As = smg;
    uint32_t* B1 = smg + 2*(128*20);
    uint32_t* B2 = B1 + 2*(16*72);
    __shared__ int srow[128];
    if (threadIdx.x < 128){
        int rr = rm + threadIdx.x;
        srow[threadIdx.x] = (rr < cnt) ? g_rows[e*TB + rr] : 0;
    }
    __syncthreads();
    const int bn = blockIdx.x*64;
    float a1[4][4][4], a2[4][4][4];
    mm_dual128(a1, a2, g_t, HD, srow,
               gw + (size_t)e*HD*ID, uw + (size_t)e*HD*ID, ID, bn, HD, As, B1, B2);
    {
        const int lane = threadIdx.x&31, warp = threadIdx.x>>5;
        const int wm = warp>>1, wn = warp&1;
#pragma unroll
        for (int im = 0; im < 4; im++)
#pragma unroll
            for (int in = 0; in < 4; in++)
#pragma unroll
                for (int h = 0; h < 2; h++)
#pragma unroll
                    for (int g2 = 0; g2 < 2; g2++){
                        const int r = rm + wm*64+im*16+(lane>>2)+h*8;
                        if (r >= cnt) continue;
                        const int c = bn + wn*32+in*8+(lane&3)*2+g2;
                        float g = a1[im][in][h*2+g2] + gb[(size_t)e*ID + c];
                        float u = a2[im][in][h*2+g2] + ub[(size_t)e*ID + c];
                        g_act[((size_t)e*TB + r)*ID + c] = (g/(1.f+__expf(-g)))*u;
                    }
    }
}

__global__ void __launch_bounds__(128,2) k_down(const float* __restrict__ dw,
                                                const float* __restrict__ db)
{
    const int e = blockIdx.z, cnt = g_cnt[e], rm = blockIdx.y*128;
    if (rm >= cnt) return;
    __shared__ uint32_t sm[SMW_NN4];
    const int bn = blockIdx.x*128;
    float acc[4][8][4];
    mm_down(acc, g_act + (size_t)e*TB*ID, ID, rm,
            dw + (size_t)e*ID*HD, HD, bn, ID, sm, sm + 2*(128*20));
    {
        const int lane = threadIdx.x&31, warp = threadIdx.x>>5;
        const int wm = warp>>1, wn = warp&1;
#pragma unroll
        for (int im = 0; im < 4; im++)
#pragma unroll
            for (int in = 0; in < 8; in++)
#pragma unroll
                for (int h = 0; h < 2; h++)
#pragma unroll
                    for (int g2 = 0; g2 < 2; g2++){
                        const int r = rm + wm*64+im*16+(lane>>2)+h*8;
                        if (r >= cnt) continue;
                        const int c = bn + wn*64+in*8+(lane&3)*2+g2;
                        g_dn[((size_t)e*TB + r)*HD + c] =
                            acc[im][in][h*2+g2] + db[(size_t)e*HD + c];
                    }
    }
}

// ---- elementwise / small kernels ----
__global__ void k_dummy(){}

__device__ __forceinline__ void rms_body(const float* __restrict__ x,
    const float* __restrict__ w, float* __restrict__ o)
{
    const int t = blockIdx.x, tid = threadIdx.x;
    const float* xr = x + (size_t)t*HD;
    float s = 0.f;
    for (int i = tid; i < HD; i += 256){ float v = xr[i]; s += v*v; }
    __shared__ float red[256];
    red[tid] = s; __syncthreads();
    for (int st = 128; st > 0; st >>= 1){ if (tid < st) red[tid] += red[tid+st]; __syncthreads(); }
    const float inv = rsqrtf(red[0]*(1.f/1024.f) + 1.1920929e-07f);
    for (int i = tid; i < HD; i += 256)
        o[(size_t)t*HD + i] = xr[i]*inv*w[i];
}
__global__ void __launch_bounds__(256) k_rms1(const float* x, const float* w){ rms_body(x, w, g_h); }
__global__ void __launch_bounds__(256) k_rms2(const float* w){ rms_body(g_x2, w, g_t); }

__global__ void __launch_bounds__(256) k_softmax()
{
    const int row = blockIdx.x*8 + (threadIdx.x>>5), lane = threadIdx.x&31;
    float4* p = (float4*)(g_sc + (size_t)row*SEQ);
    float4 v[4]; float mx = -3.402823e38f;
#pragma unroll
    for (int i=0;i<4;i++){ v[i]=p[lane+32*i];
        mx = fmaxf(mx, fmaxf(fmaxf(v[i].x,v[i].y), fmaxf(v[i].z,v[i].w))); }
#pragma unroll
    for (int o=16;o>0;o>>=1) mx = fmaxf(mx, __shfl_xor_sync(~0u, mx, o));
    float sum = 0.f;
#pragma unroll
    for (int i=0;i<4;i++){
        v[i].x=__expf(v[i].x-mx); v[i].y=__expf(v[i].y-mx);
        v[i].z=__expf(v[i].z-mx); v[i].w=__expf(v[i].w-mx);
        sum += v[i].x+v[i].y+v[i].z+v[i].w; }
#pragma unroll
    for (int o=16;o>0;o>>=1) sum += __shfl_xor_sync(~0u, sum, o);
    const float inv = 1.f/sum;
#pragma unroll
    for (int i=0;i<4;i++){ v[i].x*=inv; v[i].y*=inv; v[i].z*=inv; v[i].w*=inv; p[lane+32*i]=v[i]; }
}

__global__ void k_zero(){ if (threadIdx.x < NE) g_cnt[threadIdx.x] = 0; }

__global__ void __launch_bounds__(256) k_router(const float* __restrict__ rw,
    const float* __restrict__ rb)
{
    const int t = blockIdx.x, tid = threadIdx.x;
    const float* x = g_t + (size_t)t*HD;
    const int e = tid & 7, ch = tid >> 3;
    float s = 0.f;
    for (int i = ch*32; i < ch*32+32; i++) s += x[i]*rw[i*NE + e];
    __shared__ float part[32][9];
    __shared__ float sl[8];
    part[ch][e] = s; __syncthreads();
    if (tid < 8){
        float l = rb[tid];
        for (int c2 = 0; c2 < 32; c2++) l += part[c2][tid];
        sl[tid] = l;
    }
    __syncthreads();
    if (tid == 0){
        int e0 = 0; float v0 = sl[0];
        for (int i = 1; i < 8; i++) if (sl[i] > v0){ v0 = sl[i]; e0 = i; }
        int e1 = -1; float v1 = -3.402823e38f;
        for (int i = 0; i < 8; i++){ if (i == e0) continue; if (sl[i] > v1){ v1 = sl[i]; e1 = i; } }
        const float z = __expf(v1 - v0);
        const float p0 = 1.f/(1.f+z), p1 = z/(1.f+z);
        const int r0 = atomicAdd(&g_cnt[e0], 1);
        const int r1 = atomicAdd(&g_cnt[e1], 1);
        g_rows[e0*TB + r0] = t; g_rows[e1*TB + r1] = t;
        g_se[t*2+0] = e0; g_sr[t*2+0] = r0; g_sp[t*2+0] = p0;
        g_se[t*2+1] = e1; g_sr[t*2+1] = r1; g_sp[t*2+1] = p1;
    }
}

__global__ void __launch_bounds__(256) k_combine(float* __restrict__ out)
{
    const int t = blockIdx.x, tid = threadIdx.x;
    const int e0 = g_se[t*2+0], r0 = g_sr[t*2+0];
    const int e1 = g_se[t*2+1], r1 = g_sr[t*2+1];
    const float p0 = g_sp[t*2+0], p1 = g_sp[t*2+1];
    const float* d0 = g_dn + ((size_t)e0*TB + r0)*HD;
    const float* d1 = g_dn + ((size_t)e1*TB + r1)*HD;
    const float* xr = g_x2 + (size_t)t*HD;
    for (int i = tid; i < HD; i += 256)
        out[(size_t)t*HD + i] = xr[i] + p0*d0[i] + p1*d1[i];
}

// ---- launcher ----
extern "C" void kernel_launch(void* const* d_in, const int* in_sizes, int n_in,
                              void* d_out, int out_size)
{
    (void)in_sizes; (void)n_in; (void)out_size;
    const float* x   = (const float*)d_in[0];
    const float* n1w = (const float*)d_in[1];
    const float* qw  = (const float*)d_in[2];
    const float* qb  = (const float*)d_in[3];
    const float* kw  = (const float*)d_in[4];
    const float* kb  = (const float*)d_in[5];
    const float* vw  = (const float*)d_in[6];
    const float* vb  = (const float*)d_in[7];
    const float* ow  = (const float*)d_in[8];
    const float* ob  = (const float*)d_in[9];
    const float* n2w = (const float*)d_in[10];
    const float* rw  = (const float*)d_in[11];
    const float* rb  = (const float*)d_in[12];
    const float* gw  = (const float*)d_in[13];
    const float* gb  = (const float*)d_in[14];
    const float* uw  = (const float*)d_in[15];
    const float* ub  = (const float*)d_in[16];
    const float* dw  = (const float*)d_in[17];
    const float* db  = (const float*)d_in[18];
    float* out = (float*)d_out;

    // launches 1-3 (independent) so that launch #4 = k_qkv gets the ncu capture
    k_zero<<<1, 32>>>();
    k_rms1<<<TB, 256>>>(x, n1w);
    k_dummy<<<1, 32>>>();
    k_qkv<<<dim3(12, 8), 256>>>(qw, qb, kw, kb, vw, vb);
    k_scores<<<dim3(4, 4, NB*NHQ), 256>>>();
    k_softmax<<<NB*NHQ*SEQ/8, 256>>>();
    k_pv<<<dim3(4, NB*NHQ), 256>>>();
    k_oproj<<<dim3(8, 8), 256>>>(ow, ob, x);
    k_rms2<<<TB, 256>>>(n2w);
    k_router<<<TB, 256>>>(rw, rb);
    k_guf<<<dim3(ID/64, 8, NE), 128>>>(gw, uw, gb, ub);
    k_down<<<dim3(HD/128, 8, NE), 128>>>(dw, db);
    k_combine<<<TB, 256>>>(out);
}